// round 9
// baseline (speedup 1.0000x reference)
#include <cuda_runtime.h>
#include <cuda_bf16.h>

// ---------------------------------------------------------------------------
// Round 9: R8 core (256 thr, 2x4 warps, 64x32 warp tiles, 64B-pitch XOR
// swizzle, 128 regs, 2 CTAs/SM) + 3-stage cp.async ring (wait_group(1) in
// steady state: load-drain off the critical path) + kv K-split x2 with fp32
// partials & merge (kv grid 128 -> 256 CTAs).
// mma.sync.m16n8k16 bf16 split-hi/lo (hh+hl+lh). t' = m*1024 + w.
// ---------------------------------------------------------------------------

typedef unsigned int u32;

// ---------------- device buffers (bf16 hi/lo splits) -----------------------
__device__ __nv_bfloat16 g_Xh[2L * 16384 * 256], g_Xl[2L * 16384 * 256];
__device__ __nv_bfloat16 g_VTh[2L * 256 * 16384], g_VTl[2L * 256 * 16384];
__device__ __nv_bfloat16 g_WkTh[256 * 256], g_WkTl[256 * 256];
__device__ __nv_bfloat16 g_WqTh[256 * 256], g_WqTl[256 * 256];
__device__ __nv_bfloat16 g_PKh[2L * 256 * 16384], g_PKl[2L * 256 * 16384];
__device__ __nv_bfloat16 g_PQh[2L * 1024 * 256], g_PQl[2L * 1024 * 256];
__device__ __nv_bfloat16 g_KVh[2L * 4096 * 256], g_KVl[2L * 4096 * 256];
__device__ float g_KVp[2L * 2 * 4096 * 256];     // 2 K-slices, fp32 partials

// ---------------- smem geometry -------------------------------------------
// One stage = 4 tiles (Ah, Al, Bh, Bl), each 128 rows x 64B, XOR-swizzled:
// phys = row*64 + ((chunk16 ^ ((row>>1)&3)) << 4). 3 stages.
#define TILE_B   8192                  // 128 * 64
#define STAGE_B  (4 * TILE_B)          // 32768
#define NSTAGE   3
#define SM_PS    (NSTAGE * STAGE_B)    // 98304 (Cs 128*132*4=67584 fits under)
#define SMEM_BYTES (SM_PS + 1024)      // 99328 -> 2 CTAs/SM (198656 < 228K)

// ---------------- PTX helpers ---------------------------------------------
__device__ __forceinline__ u32 smem_u32(const void* p) {
    u32 a;
    asm("{ .reg .u64 t; cvta.to.shared.u64 t, %1; cvt.u32.u64 %0, t; }"
        : "=r"(a) : "l"(p));
    return a;
}
__device__ __forceinline__ void cp_async16(u32 dst, const void* src) {
    asm volatile("cp.async.cg.shared.global [%0], [%1], 16;"
                 :: "r"(dst), "l"(src));
}
#define CP_COMMIT() asm volatile("cp.async.commit_group;" ::: "memory")
#define CP_WAIT(n)  asm volatile("cp.async.wait_group %0;" :: "n"(n) : "memory")

__device__ __forceinline__ void ldmx4(u32& r0, u32& r1, u32& r2, u32& r3, u32 a) {
    asm volatile("ldmatrix.sync.aligned.m8n8.x4.shared.b16 {%0,%1,%2,%3}, [%4];"
                 : "=r"(r0), "=r"(r1), "=r"(r2), "=r"(r3) : "r"(a));
}
__device__ __forceinline__ void mma_bf16(float* c, const u32* a, const u32* b) {
    asm volatile(
        "mma.sync.aligned.m16n8k16.row.col.f32.bf16.bf16.f32 "
        "{%0,%1,%2,%3}, {%4,%5,%6,%7}, {%8,%9}, {%0,%1,%2,%3};"
        : "+f"(c[0]), "+f"(c[1]), "+f"(c[2]), "+f"(c[3])
        : "r"(a[0]), "r"(a[1]), "r"(a[2]), "r"(a[3]), "r"(b[0]), "r"(b[1]));
}

__device__ __forceinline__ float phi_act(float z) {
    return z > 0.f ? z + 2.f : __expf(z) + 1.f;
}
__device__ __forceinline__ void split1(float x, __nv_bfloat16& h, __nv_bfloat16& l) {
    h = __float2bfloat16(x);
    l = __float2bfloat16(x - __bfloat162float(h));
}
__device__ __forceinline__ u32 pack_bf2(__nv_bfloat16 a, __nv_bfloat16 b) {
    __nv_bfloat162 p; p.x = a; p.y = b;
    return *(u32*)&p;
}
// swizzled in-tile byte offset for (row, chunk16)
__device__ __forceinline__ u32 swz(u32 row, u32 c) {
    return row * 64 + ((c ^ ((row >> 1) & 3)) << 4);
}

// ---------------------------------------------------------------------------
// Core mainloop: acc(128x128 f32, per-warp 64x32) += A(128xK) * B(128xK)^T
// split-bf16 3-term. K = NB*32. 3-stage ring, one barrier per k-step,
// steady-state wait_group(1).
// ---------------------------------------------------------------------------
__device__ __forceinline__ void run_gemm(
    char* sm, u32 smb,
    const __nv_bfloat16* __restrict__ Ah, const __nv_bfloat16* __restrict__ Al, long sA,
    const __nv_bfloat16* __restrict__ Bh, const __nv_bfloat16* __restrict__ Bl, long sB,
    int NB, float acc[4][4][4])
{
    const int tid = threadIdx.x, wid = tid >> 5, lane = tid & 31;
    const int warp_m = (wid & 1) * 64, warp_n = (wid >> 1) * 32;

    auto issue_stage = [&](int s, int kb) {
        u32 base = smb + s * STAGE_B;
#pragma unroll
        for (int i = 0; i < 8; i++) {
            int ch = i * 256 + tid;                // 2048 chunks of 16B
            int tile = ch >> 9;
            u32 row = (ch >> 2) & 127, kc = ch & 3;
            const __nv_bfloat16* gb =
                (tile == 0) ? Ah : (tile == 1) ? Al : (tile == 2) ? Bh : Bl;
            long st = (tile < 2) ? sA : sB;
            cp_async16(base + tile * TILE_B + swz(row, kc),
                       gb + (long)row * st + (long)kb * 32 + kc * 8);
        }
        CP_COMMIT();
    };

    // per-thread ldmatrix row/chunk decomposition
    const u32 arow = warp_m + (lane & 15);
    const u32 ac   = lane >> 4;                    // chunk bit0
    const u32 brow = warp_n + (lane & 7) + ((lane >> 4) << 3);
    const u32 bc   = (lane >> 3) & 1;

    issue_stage(0, 0);
    if (NB > 1) issue_stage(1, 1);

    int sc = 0;        // stage of kb
    int si = 2;        // stage of kb+2
    for (int kb = 0; kb < NB; kb++) {
        if (kb + 1 < NB) CP_WAIT(1);
        else             CP_WAIT(0);
        __syncthreads();
        if (kb + 2 < NB) issue_stage(si, kb + 2);

        u32 sb = smb + sc * STAGE_B;
        sc = (sc == 2) ? 0 : sc + 1;
        si = (si == 2) ? 0 : si + 1;

#pragma unroll
        for (int kh = 0; kh < 2; kh++) {
            u32 ah[4][4], al[4][4], bh[4][2], bl[4][2];
            const u32 aoff = swz(arow, ac + kh * 2);
            const u32 boff = swz(brow, bc + kh * 2);
#pragma unroll
            for (int i = 0; i < 4; i++) {
                ldmx4(ah[i][0], ah[i][1], ah[i][2], ah[i][3],
                      sb + aoff + i * 1024);
                ldmx4(al[i][0], al[i][1], al[i][2], al[i][3],
                      sb + TILE_B + aoff + i * 1024);
            }
#pragma unroll
            for (int j = 0; j < 2; j++) {
                ldmx4(bh[2 * j][0], bh[2 * j][1], bh[2 * j + 1][0], bh[2 * j + 1][1],
                      sb + 2 * TILE_B + boff + j * 1024);
                ldmx4(bl[2 * j][0], bl[2 * j][1], bl[2 * j + 1][0], bl[2 * j + 1][1],
                      sb + 3 * TILE_B + boff + j * 1024);
            }
#pragma unroll
            for (int i = 0; i < 4; i++)
#pragma unroll
                for (int j = 0; j < 4; j++) {
                    mma_bf16(acc[i][j], ah[i], bh[j]);
                    mma_bf16(acc[i][j], ah[i], bl[j]);
                    mma_bf16(acc[i][j], al[i], bh[j]);
                }
        }
    }
    __syncthreads();   // protect smem before epilogue staging reuses it
}

// Store per-warp accumulators into Cs[128][132] f32 (reuses stage memory).
__device__ __forceinline__ void stage_C(char* sm, float acc[4][4][4])
{
    const int tid = threadIdx.x, wid = tid >> 5, lane = tid & 31;
    const int warp_m = (wid & 1) * 64, warp_n = (wid >> 1) * 32;
    float* Cs = (float*)sm;
#pragma unroll
    for (int i = 0; i < 4; i++)
#pragma unroll
        for (int j = 0; j < 4; j++) {
            int r = warp_m + i * 16 + (lane >> 2);
            int c = warp_n + j * 8 + (lane & 3) * 2;
            *(float2*)&Cs[r * 132 + c] =
                make_float2(acc[i][j][0], acc[i][j][1]);
            *(float2*)&Cs[(r + 8) * 132 + c] =
                make_float2(acc[i][j][2], acc[i][j][3]);
        }
    __syncthreads();
}

#define ACC_DECL() float acc[4][4][4];                                   \
    _Pragma("unroll") for (int i = 0; i < 4; i++)                        \
    _Pragma("unroll") for (int j = 0; j < 4; j++)                        \
    _Pragma("unroll") for (int e = 0; e < 4; e++) acc[i][j][e] = 0.f;

// ---------------------------------------------------------------------------
// proj kernel: blockIdx.x<256 -> K-projection (M=c, N=tokens),
//              else            -> Q-projection (M=r, N=c).  K=256 (NB=8).
// ---------------------------------------------------------------------------
__global__ __launch_bounds__(256) void proj_kernel(
    const float* __restrict__ bk, const float* __restrict__ bq)
{
    extern __shared__ char sm[];
    u32 smb = smem_u32(sm);
    const int tid = threadIdx.x;
    const int b = blockIdx.y;
    const bool isK = blockIdx.x < 256;
    int c0, t0 = 0, r0 = 0;
    const __nv_bfloat16 *Ah, *Al, *Bh, *Bl;
    if (isK) {
        c0 = (blockIdx.x >> 7) * 128;
        t0 = (blockIdx.x & 127) * 128;
        Ah = g_WkTh + c0 * 256;  Al = g_WkTl + c0 * 256;
        Bh = g_Xh + ((long)b * 16384 + t0) * 256;
        Bl = g_Xl + ((long)b * 16384 + t0) * 256;
    } else {
        int xi = blockIdx.x - 256;
        r0 = (xi >> 1) * 128;
        c0 = (xi & 1) * 128;
        Ah = g_Xh + ((long)b * 16384 + r0) * 256;
        Al = g_Xl + ((long)b * 16384 + r0) * 256;
        Bh = g_WqTh + c0 * 256;  Bl = g_WqTl + c0 * 256;
    }

    ACC_DECL();
    run_gemm(sm, smb, Ah, Al, 256, Bh, Bl, 256, 8, acc);
    stage_C(sm, acc);
    const float* Cs = (const float*)sm;

    if (isK) {
        const int w0 = t0 >> 4;   // 8 windows in this token tile
#pragma unroll
        for (int it = 0; it < 8; it++) {
            int task = it * 256 + tid;            // 2048 = 128 c x 16 m
            int c = task >> 4, m = task & 15;
            float bias = bk[c0 + c];
            u32 H[4], L[4];
#pragma unroll
            for (int wl = 0; wl < 4; wl++) {
                float x0 = phi_act(Cs[c * 132 + (2 * wl) * 16 + m] + bias);
                float x1 = phi_act(Cs[c * 132 + (2 * wl + 1) * 16 + m] + bias);
                __nv_bfloat16 h0, l0, h1, l1;
                split1(x0, h0, l0); split1(x1, h1, l1);
                H[wl] = pack_bf2(h0, h1); L[wl] = pack_bf2(l0, l1);
            }
            long off = ((long)b * 256 + c0 + c) * 16384 + m * 1024 + w0;
            *(uint4*)(g_PKh + off) = make_uint4(H[0], H[1], H[2], H[3]);
            *(uint4*)(g_PKl + off) = make_uint4(L[0], L[1], L[2], L[3]);
        }
    } else {
#pragma unroll
        for (int it = 0; it < 8; it++) {
            int task = it * 256 + tid;            // 2048 = 128 r x 16 chunks
            int r = task >> 4, ch = task & 15;
            u32 H[4], L[4];
#pragma unroll
            for (int p = 0; p < 4; p++) {
                int col = ch * 8 + 2 * p;
                float x0 = phi_act(Cs[r * 132 + col] + bq[c0 + col]);
                float x1 = phi_act(Cs[r * 132 + col + 1] + bq[c0 + col + 1]);
                __nv_bfloat16 h0, l0, h1, l1;
                split1(x0, h0, l0); split1(x1, h1, l1);
                H[p] = pack_bf2(h0, h1); L[p] = pack_bf2(l0, l1);
            }
            long off = ((long)b * 1024 + r0 + r) * 256 + c0 + ch * 8;
            *(uint4*)(g_PQh + off) = make_uint4(H[0], H[1], H[2], H[3]);
            *(uint4*)(g_PQl + off) = make_uint4(L[0], L[1], L[2], L[3]);
        }
    }
}

// ---------------------------------------------------------------------------
// kv kernel (partial): one 512-token K-slice of
// KVT[b][m*256+d][c] = sum_{t'} VT[d][t'] phiKT[c][t'].
// grid (dtile=2, ctile=2, slice*32 + b*16 + m), NB=16. fp32 partial output.
// ---------------------------------------------------------------------------
__global__ __launch_bounds__(256) void kv_kernel()
{
    extern __shared__ char sm[];
    u32 smb = smem_u32(sm);
    const int tid = threadIdx.x;
    const int zz = blockIdx.z;
    const int slice = zz >> 5, bm = zz & 31;
    const int b = bm >> 4, m = bm & 15;
    const int d0 = blockIdx.x * 128, c0 = blockIdx.y * 128;
    const long abase = ((long)b * 256 + d0) * 16384 + m * 1024 + slice * 512;
    const long bbase = ((long)b * 256 + c0) * 16384 + m * 1024 + slice * 512;

    ACC_DECL();
    run_gemm(sm, smb, g_VTh + abase, g_VTl + abase, 16384,
             g_PKh + bbase, g_PKl + bbase, 16384, 16, acc);
    stage_C(sm, acc);
    const float* Cs = (const float*)sm;

    float* dstS = g_KVp + (long)slice * (2L * 4096 * 256);
#pragma unroll
    for (int it = 0; it < 8; it++) {
        int task = it * 256 + tid;                // 2048 = 128 d x 16 chunks
        int d = task >> 4, ch = task & 15;
        float* dst = dstS + ((long)b * 4096 + m * 256 + d0 + d) * 256 + c0 + ch * 8;
        *(float4*)(dst)     = *(const float4*)&Cs[d * 132 + ch * 8];
        *(float4*)(dst + 4) = *(const float4*)&Cs[d * 132 + ch * 8 + 4];
    }
}

// ---------------------------------------------------------------------------
// kv merge: sum 2 fp32 slices, split to bf16 hi/lo. 2M elements.
// ---------------------------------------------------------------------------
__global__ __launch_bounds__(256) void kv_merge_kernel()
{
    const long S = 2L * 4096 * 256;
    long i = (long)blockIdx.x * 256 + threadIdx.x;   // float4 index
    float4 a0 = ((const float4*)g_KVp)[i];
    float4 a1 = ((const float4*)(g_KVp + S))[i];
    float f[4] = { a0.x + a1.x, a0.y + a1.y, a0.z + a1.z, a0.w + a1.w };
    __nv_bfloat16 h0, l0, h1, l1, h2, l2, h3, l3;
    split1(f[0], h0, l0); split1(f[1], h1, l1);
    split1(f[2], h2, l2); split1(f[3], h3, l3);
    ((uint2*)g_KVh)[i] = make_uint2(pack_bf2(h0, h1), pack_bf2(h2, h3));
    ((uint2*)g_KVl)[i] = make_uint2(pack_bf2(l0, l1), pack_bf2(l2, l3));
}

// ---------------------------------------------------------------------------
// att kernel: out[b][w*256+n*16+m][d] = sum_c phiQ[r][c] KVT[m*256+d][c] + p.
// grid (rtile=8, jtile=32, b). K=256 (NB=8).
// ---------------------------------------------------------------------------
__global__ __launch_bounds__(256) void att_kernel(
    const float* __restrict__ embed, const float* __restrict__ Wp,
    const float* __restrict__ bp, float* __restrict__ out)
{
    extern __shared__ char sm[];
    u32 smb = smem_u32(sm);
    const int tid = threadIdx.x;
    const int b = blockIdx.z;
    const int r0 = blockIdx.x * 128;
    const int j0 = blockIdx.y * 128;
    const int m = j0 >> 8, d0 = j0 & 255;
    const long abase = ((long)b * 1024 + r0) * 256;
    const long bbase = ((long)b * 4096 + j0) * 256;

    if (tid < 128) {
        int r = r0 + tid, w = r >> 4, n = r & 15;
        const float* e = embed + ((((long)b * 1024 + w) * 16 + n) * 16 + m) * 3;
        ((float*)(sm + SM_PS))[tid] =
            e[0] * Wp[0] + e[1] * Wp[1] + e[2] * Wp[2] + bp[0];
    }

    ACC_DECL();
    run_gemm(sm, smb, g_PQh + abase, g_PQl + abase, 256,
             g_KVh + bbase, g_KVl + bbase, 256, 8, acc);
    stage_C(sm, acc);
    const float* Cs = (const float*)sm;

#pragma unroll
    for (int it = 0; it < 16; it++) {
        int task = it * 256 + tid;                // 4096 = 128 r x 32 f4-chunks
        int r = task >> 5, ch = task & 31;
        float4 v = *(const float4*)&Cs[r * 132 + ch * 4];
        float p = ((const float*)(sm + SM_PS))[r];
        v.x += p; v.y += p; v.z += p; v.w += p;
        int rg = r0 + r, w = rg >> 4, n = rg & 15;
        long t = (long)w * 256 + n * 16 + m;
        *(float4*)(out + ((long)b * 16384 + t) * 256 + d0 + ch * 4) = v;
    }
}

// ---------------------------------------------------------------------------
// prep kernels
// ---------------------------------------------------------------------------
__global__ __launch_bounds__(256) void prep_split(const float* __restrict__ X)
{
    long i = (long)blockIdx.x * 256 + threadIdx.x;   // float4 index
    float4 v = ((const float4*)X)[i];
    __nv_bfloat16 h0, l0, h1, l1, h2, l2, h3, l3;
    split1(v.x, h0, l0); split1(v.y, h1, l1);
    split1(v.z, h2, l2); split1(v.w, h3, l3);
    ((uint2*)g_Xh)[i] = make_uint2(pack_bf2(h0, h1), pack_bf2(h2, h3));
    ((uint2*)g_Xl)[i] = make_uint2(pack_bf2(l0, l1), pack_bf2(l2, l3));
}

// VT[b][d][m*1024+w] = X[b][w*16+m][d]; grid (wtile=32, dtile=8, b*16+m)
__global__ __launch_bounds__(256) void prep_vt(const float* __restrict__ X)
{
    __shared__ float tile[32][33];
    const int bm = blockIdx.z, b = bm >> 4, m = bm & 15;
    const int w0 = blockIdx.x * 32, d0 = blockIdx.y * 32;
    const int dx = threadIdx.x & 31, dy = threadIdx.x >> 5;
#pragma unroll
    for (int p = 0; p < 4; p++) {
        int w = w0 + dy + p * 8;
        tile[dy + p * 8][dx] =
            X[((long)b * 16384 + (long)w * 16 + m) * 256 + d0 + dx];
    }
    __syncthreads();
#pragma unroll
    for (int p = 0; p < 4; p++) {
        int d = d0 + dy + p * 8;
        float v = tile[dx][dy + p * 8];
        __nv_bfloat16 h, l; split1(v, h, l);
        long off = ((long)b * 256 + d) * 16384 + m * 1024 + w0 + dx;
        g_VTh[off] = h; g_VTl[off] = l;
    }
}

// WT[n][k] = W[k][n]; grid (ktile=8, ntile=8, 2: 0=Wk,1=Wq)
__global__ __launch_bounds__(256) void prep_w(
    const float* __restrict__ Wk, const float* __restrict__ Wq)
{
    __shared__ float tile[32][33];
    const int isQ = blockIdx.z;
    const float* W = isQ ? Wq : Wk;
    __nv_bfloat16* TH = isQ ? g_WqTh : g_WkTh;
    __nv_bfloat16* TL = isQ ? g_WqTl : g_WkTl;
    const int k0 = blockIdx.x * 32, n0 = blockIdx.y * 32;
    const int dx = threadIdx.x & 31, dy = threadIdx.x >> 5;
#pragma unroll
    for (int p = 0; p < 4; p++)
        tile[dy + p * 8][dx] = W[(k0 + dy + p * 8) * 256 + n0 + dx];
    __syncthreads();
#pragma unroll
    for (int p = 0; p < 4; p++) {
        float v = tile[dx][dy + p * 8];
        __nv_bfloat16 h, l; split1(v, h, l);
        int off = (n0 + dy + p * 8) * 256 + k0 + dx;
        TH[off] = h; TL[off] = l;
    }
}

// ---------------------------------------------------------------------------
// Inputs (metadata order): input, embed_qk, Wq, bq, Wk, bk, Wp, bp
// ---------------------------------------------------------------------------
extern "C" void kernel_launch(void* const* d_in, const int* in_sizes, int n_in,
                              void* d_out, int out_size)
{
    const float* input = (const float*)d_in[0];
    const float* embed = (const float*)d_in[1];
    const float* Wq    = (const float*)d_in[2];
    const float* bq    = (const float*)d_in[3];
    const float* Wk    = (const float*)d_in[4];
    const float* bk    = (const float*)d_in[5];
    const float* Wp    = (const float*)d_in[6];
    const float* bp    = (const float*)d_in[7];
    float* out = (float*)d_out;

    cudaFuncSetAttribute(proj_kernel, cudaFuncAttributeMaxDynamicSharedMemorySize, SMEM_BYTES);
    cudaFuncSetAttribute(kv_kernel,   cudaFuncAttributeMaxDynamicSharedMemorySize, SMEM_BYTES);
    cudaFuncSetAttribute(att_kernel,  cudaFuncAttributeMaxDynamicSharedMemorySize, SMEM_BYTES);

    prep_split<<<8192, 256>>>(input);
    prep_vt<<<dim3(32, 8, 32), 256>>>(input);
    prep_w<<<dim3(8, 8, 2), 256>>>(Wk, Wq);

    proj_kernel<<<dim3(272, 2), 256, SMEM_BYTES>>>(bk, bq);
    kv_kernel<<<dim3(2, 2, 64), 256, SMEM_BYTES>>>();
    kv_merge_kernel<<<2048, 256>>>();
    att_kernel<<<dim3(8, 32, 2), 256, SMEM_BYTES>>>(embed, Wp, bp, out);
}

// round 10
// speedup vs baseline: 1.0644x; 1.0644x over previous
#include <cuda_runtime.h>
#include <cuda_bf16.h>

// ---------------------------------------------------------------------------
// Round 10: exact R8 GEMM configuration (best: 173.7us) + fused prep:
//   * prep kernel = VT transpose + X hi/lo split + W transpose in ONE launch
//     (removes prep_split's 33.5MB X re-read and two kernel launches)
// Core: 256 thr, 2x4 warps, 64x32 warp tiles, 64B-pitch XOR swizzle,
// 2-stage cp.async, single barrier/k-step, 128 regs, 2 CTAs/SM.
// mma.sync.m16n8k16 bf16 split-hi/lo (hh+hl+lh). t' = m*1024 + w.
// ---------------------------------------------------------------------------

typedef unsigned int u32;

// ---------------- device buffers (bf16 hi/lo splits) -----------------------
__device__ __nv_bfloat16 g_Xh[2L * 16384 * 256], g_Xl[2L * 16384 * 256];
__device__ __nv_bfloat16 g_VTh[2L * 256 * 16384], g_VTl[2L * 256 * 16384];
__device__ __nv_bfloat16 g_WkTh[256 * 256], g_WkTl[256 * 256];
__device__ __nv_bfloat16 g_WqTh[256 * 256], g_WqTl[256 * 256];
__device__ __nv_bfloat16 g_PKh[2L * 256 * 16384], g_PKl[2L * 256 * 16384];
__device__ __nv_bfloat16 g_PQh[2L * 1024 * 256], g_PQl[2L * 1024 * 256];
__device__ __nv_bfloat16 g_KVh[2L * 4096 * 256], g_KVl[2L * 4096 * 256];

// ---------------- smem geometry -------------------------------------------
// One stage = 4 tiles (Ah, Al, Bh, Bl), each 128 rows x 64B, XOR-swizzled:
// phys = row*64 + ((chunk16 ^ ((row>>1)&3)) << 4).
#define TILE_B   8192                  // 128 * 64
#define STAGE_B  (4 * TILE_B)          // 32768
#define SM_PS    67712                 // scratch after Cs (128*132*4=67584)
#define SMEM_BYTES (SM_PS + 1024)      // 68736 -> 2 CTAs/SM

// ---------------- PTX helpers ---------------------------------------------
__device__ __forceinline__ u32 smem_u32(const void* p) {
    u32 a;
    asm("{ .reg .u64 t; cvta.to.shared.u64 t, %1; cvt.u32.u64 %0, t; }"
        : "=r"(a) : "l"(p));
    return a;
}
__device__ __forceinline__ void cp_async16(u32 dst, const void* src) {
    asm volatile("cp.async.cg.shared.global [%0], [%1], 16;"
                 :: "r"(dst), "l"(src));
}
#define CP_COMMIT() asm volatile("cp.async.commit_group;" ::: "memory")
#define CP_WAIT(n)  asm volatile("cp.async.wait_group %0;" :: "n"(n) : "memory")

__device__ __forceinline__ void ldmx4(u32& r0, u32& r1, u32& r2, u32& r3, u32 a) {
    asm volatile("ldmatrix.sync.aligned.m8n8.x4.shared.b16 {%0,%1,%2,%3}, [%4];"
                 : "=r"(r0), "=r"(r1), "=r"(r2), "=r"(r3) : "r"(a));
}
__device__ __forceinline__ void mma_bf16(float* c, const u32* a, const u32* b) {
    asm volatile(
        "mma.sync.aligned.m16n8k16.row.col.f32.bf16.bf16.f32 "
        "{%0,%1,%2,%3}, {%4,%5,%6,%7}, {%8,%9}, {%0,%1,%2,%3};"
        : "+f"(c[0]), "+f"(c[1]), "+f"(c[2]), "+f"(c[3])
        : "r"(a[0]), "r"(a[1]), "r"(a[2]), "r"(a[3]), "r"(b[0]), "r"(b[1]));
}

__device__ __forceinline__ float phi_act(float z) {
    return z > 0.f ? z + 2.f : __expf(z) + 1.f;
}
__device__ __forceinline__ void split1(float x, __nv_bfloat16& h, __nv_bfloat16& l) {
    h = __float2bfloat16(x);
    l = __float2bfloat16(x - __bfloat162float(h));
}
__device__ __forceinline__ u32 pack_bf2(__nv_bfloat16 a, __nv_bfloat16 b) {
    __nv_bfloat162 p; p.x = a; p.y = b;
    return *(u32*)&p;
}
// swizzled in-tile byte offset for (row, chunk16)
__device__ __forceinline__ u32 swz(u32 row, u32 c) {
    return row * 64 + ((c ^ ((row >> 1) & 3)) << 4);
}

// ---------------------------------------------------------------------------
// Core mainloop: acc(128x128 f32, per-warp 64x32) += A(128xK) * B(128xK)^T
// split-bf16 3-term. K = NB*32. 2-stage buffer, ONE barrier per k-step.
// ---------------------------------------------------------------------------
__device__ __forceinline__ void run_gemm(
    char* sm, u32 smb,
    const __nv_bfloat16* __restrict__ Ah, const __nv_bfloat16* __restrict__ Al, long sA,
    const __nv_bfloat16* __restrict__ Bh, const __nv_bfloat16* __restrict__ Bl, long sB,
    int NB, float acc[4][4][4])
{
    const int tid = threadIdx.x, wid = tid >> 5, lane = tid & 31;
    const int warp_m = (wid & 1) * 64, warp_n = (wid >> 1) * 32;

    auto issue_stage = [&](int s, int kb) {
        u32 base = smb + s * STAGE_B;
#pragma unroll
        for (int i = 0; i < 8; i++) {
            int ch = i * 256 + tid;                // 2048 chunks of 16B
            int tile = ch >> 9;
            u32 row = (ch >> 2) & 127, kc = ch & 3;
            const __nv_bfloat16* gb =
                (tile == 0) ? Ah : (tile == 1) ? Al : (tile == 2) ? Bh : Bl;
            long st = (tile < 2) ? sA : sB;
            cp_async16(base + tile * TILE_B + swz(row, kc),
                       gb + (long)row * st + (long)kb * 32 + kc * 8);
        }
        CP_COMMIT();
    };

    // per-thread ldmatrix row/chunk decomposition
    const u32 arow = warp_m + (lane & 15);
    const u32 ac   = lane >> 4;                    // chunk bit0
    const u32 brow = warp_n + (lane & 7) + ((lane >> 4) << 3);
    const u32 bc   = (lane >> 3) & 1;

    issue_stage(0, 0);

    for (int kb = 0; kb < NB; kb++) {
        CP_WAIT(0);
        __syncthreads();
        if (kb + 1 < NB) issue_stage((kb + 1) & 1, kb + 1);

        u32 sb = smb + (kb & 1) * STAGE_B;

#pragma unroll
        for (int kh = 0; kh < 2; kh++) {
            u32 ah[4][4], al[4][4], bh[4][2], bl[4][2];
            const u32 aoff = swz(arow, ac + kh * 2);
            const u32 boff = swz(brow, bc + kh * 2);
#pragma unroll
            for (int i = 0; i < 4; i++) {
                ldmx4(ah[i][0], ah[i][1], ah[i][2], ah[i][3],
                      sb + aoff + i * 1024);
                ldmx4(al[i][0], al[i][1], al[i][2], al[i][3],
                      sb + TILE_B + aoff + i * 1024);
            }
#pragma unroll
            for (int j = 0; j < 2; j++) {
                ldmx4(bh[2 * j][0], bh[2 * j][1], bh[2 * j + 1][0], bh[2 * j + 1][1],
                      sb + 2 * TILE_B + boff + j * 1024);
                ldmx4(bl[2 * j][0], bl[2 * j][1], bl[2 * j + 1][0], bl[2 * j + 1][1],
                      sb + 3 * TILE_B + boff + j * 1024);
            }
#pragma unroll
            for (int i = 0; i < 4; i++)
#pragma unroll
                for (int j = 0; j < 4; j++) {
                    mma_bf16(acc[i][j], ah[i], bh[j]);
                    mma_bf16(acc[i][j], ah[i], bl[j]);
                    mma_bf16(acc[i][j], al[i], bh[j]);
                }
        }
    }
    __syncthreads();   // protect smem before epilogue staging reuses it
}

// Store per-warp accumulators into Cs[128][132] f32 (reuses stage memory).
__device__ __forceinline__ void stage_C(char* sm, float acc[4][4][4])
{
    const int tid = threadIdx.x, wid = tid >> 5, lane = tid & 31;
    const int warp_m = (wid & 1) * 64, warp_n = (wid >> 1) * 32;
    float* Cs = (float*)sm;
#pragma unroll
    for (int i = 0; i < 4; i++)
#pragma unroll
        for (int j = 0; j < 4; j++) {
            int r = warp_m + i * 16 + (lane >> 2);
            int c = warp_n + j * 8 + (lane & 3) * 2;
            *(float2*)&Cs[r * 132 + c] =
                make_float2(acc[i][j][0], acc[i][j][1]);
            *(float2*)&Cs[(r + 8) * 132 + c] =
                make_float2(acc[i][j][2], acc[i][j][3]);
        }
    __syncthreads();
}

#define ACC_DECL() float acc[4][4][4];                                   \
    _Pragma("unroll") for (int i = 0; i < 4; i++)                        \
    _Pragma("unroll") for (int j = 0; j < 4; j++)                        \
    _Pragma("unroll") for (int e = 0; e < 4; e++) acc[i][j][e] = 0.f;

// ---------------------------------------------------------------------------
// proj kernel: blockIdx.x<256 -> K-projection (M=c, N=tokens),
//              else            -> Q-projection (M=r, N=c).  K=256 (NB=8).
// ---------------------------------------------------------------------------
__global__ __launch_bounds__(256) void proj_kernel(
    const float* __restrict__ bk, const float* __restrict__ bq)
{
    extern __shared__ char sm[];
    u32 smb = smem_u32(sm);
    const int tid = threadIdx.x;
    const int b = blockIdx.y;
    const bool isK = blockIdx.x < 256;
    int c0, t0 = 0, r0 = 0;
    const __nv_bfloat16 *Ah, *Al, *Bh, *Bl;
    if (isK) {
        c0 = (blockIdx.x >> 7) * 128;
        t0 = (blockIdx.x & 127) * 128;
        Ah = g_WkTh + c0 * 256;  Al = g_WkTl + c0 * 256;
        Bh = g_Xh + ((long)b * 16384 + t0) * 256;
        Bl = g_Xl + ((long)b * 16384 + t0) * 256;
    } else {
        int xi = blockIdx.x - 256;
        r0 = (xi >> 1) * 128;
        c0 = (xi & 1) * 128;
        Ah = g_Xh + ((long)b * 16384 + r0) * 256;
        Al = g_Xl + ((long)b * 16384 + r0) * 256;
        Bh = g_WqTh + c0 * 256;  Bl = g_WqTl + c0 * 256;
    }

    ACC_DECL();
    run_gemm(sm, smb, Ah, Al, 256, Bh, Bl, 256, 8, acc);
    stage_C(sm, acc);
    const float* Cs = (const float*)sm;

    if (isK) {
        const int w0 = t0 >> 4;   // 8 windows in this token tile
#pragma unroll
        for (int it = 0; it < 8; it++) {
            int task = it * 256 + tid;            // 2048 = 128 c x 16 m
            int c = task >> 4, m = task & 15;
            float bias = bk[c0 + c];
            u32 H[4], L[4];
#pragma unroll
            for (int wl = 0; wl < 4; wl++) {
                float x0 = phi_act(Cs[c * 132 + (2 * wl) * 16 + m] + bias);
                float x1 = phi_act(Cs[c * 132 + (2 * wl + 1) * 16 + m] + bias);
                __nv_bfloat16 h0, l0, h1, l1;
                split1(x0, h0, l0); split1(x1, h1, l1);
                H[wl] = pack_bf2(h0, h1); L[wl] = pack_bf2(l0, l1);
            }
            long off = ((long)b * 256 + c0 + c) * 16384 + m * 1024 + w0;
            *(uint4*)(g_PKh + off) = make_uint4(H[0], H[1], H[2], H[3]);
            *(uint4*)(g_PKl + off) = make_uint4(L[0], L[1], L[2], L[3]);
        }
    } else {
#pragma unroll
        for (int it = 0; it < 8; it++) {
            int task = it * 256 + tid;            // 2048 = 128 r x 16 chunks
            int r = task >> 4, ch = task & 15;
            u32 H[4], L[4];
#pragma unroll
            for (int p = 0; p < 4; p++) {
                int col = ch * 8 + 2 * p;
                float x0 = phi_act(Cs[r * 132 + col] + bq[c0 + col]);
                float x1 = phi_act(Cs[r * 132 + col + 1] + bq[c0 + col + 1]);
                __nv_bfloat16 h0, l0, h1, l1;
                split1(x0, h0, l0); split1(x1, h1, l1);
                H[p] = pack_bf2(h0, h1); L[p] = pack_bf2(l0, l1);
            }
            long off = ((long)b * 1024 + r0 + r) * 256 + c0 + ch * 8;
            *(uint4*)(g_PQh + off) = make_uint4(H[0], H[1], H[2], H[3]);
            *(uint4*)(g_PQl + off) = make_uint4(L[0], L[1], L[2], L[3]);
        }
    }
}

// ---------------------------------------------------------------------------
// kv kernel: KVT[b][m*256+d][c] = sum_{t'} VT[d][t'] phiKT[c][t'], K=1024.
// grid (dtile=2, ctile=2, b*16+m), NB=32.
// ---------------------------------------------------------------------------
__global__ __launch_bounds__(256) void kv_kernel()
{
    extern __shared__ char sm[];
    u32 smb = smem_u32(sm);
    const int tid = threadIdx.x;
    const int bm = blockIdx.z, b = bm >> 4, m = bm & 15;
    const int d0 = blockIdx.x * 128, c0 = blockIdx.y * 128;
    const long abase = ((long)b * 256 + d0) * 16384 + m * 1024;
    const long bbase = ((long)b * 256 + c0) * 16384 + m * 1024;

    ACC_DECL();
    run_gemm(sm, smb, g_VTh + abase, g_VTl + abase, 16384,
             g_PKh + bbase, g_PKl + bbase, 16384, 32, acc);
    stage_C(sm, acc);
    const float* Cs = (const float*)sm;

#pragma unroll
    for (int it = 0; it < 8; it++) {
        int task = it * 256 + tid;                // 2048 = 128 d x 16 chunks
        int d = task >> 4, ch = task & 15;
        u32 H[4], L[4];
#pragma unroll
        for (int p = 0; p < 4; p++) {
            float x0 = Cs[d * 132 + ch * 8 + 2 * p];
            float x1 = Cs[d * 132 + ch * 8 + 2 * p + 1];
            __nv_bfloat16 h0, l0, h1, l1;
            split1(x0, h0, l0); split1(x1, h1, l1);
            H[p] = pack_bf2(h0, h1); L[p] = pack_bf2(l0, l1);
        }
        long off = ((long)b * 4096 + m * 256 + d0 + d) * 256 + c0 + ch * 8;
        *(uint4*)(g_KVh + off) = make_uint4(H[0], H[1], H[2], H[3]);
        *(uint4*)(g_KVl + off) = make_uint4(L[0], L[1], L[2], L[3]);
    }
}

// ---------------------------------------------------------------------------
// att kernel: out[b][w*256+n*16+m][d] = sum_c phiQ[r][c] KVT[m*256+d][c] + p.
// grid (rtile=8, jtile=32, b). K=256 (NB=8).
// ---------------------------------------------------------------------------
__global__ __launch_bounds__(256) void att_kernel(
    const float* __restrict__ embed, const float* __restrict__ Wp,
    const float* __restrict__ bp, float* __restrict__ out)
{
    extern __shared__ char sm[];
    u32 smb = smem_u32(sm);
    const int tid = threadIdx.x;
    const int b = blockIdx.z;
    const int r0 = blockIdx.x * 128;
    const int j0 = blockIdx.y * 128;
    const int m = j0 >> 8, d0 = j0 & 255;
    const long abase = ((long)b * 1024 + r0) * 256;
    const long bbase = ((long)b * 4096 + j0) * 256;

    if (tid < 128) {
        int r = r0 + tid, w = r >> 4, n = r & 15;
        const float* e = embed + ((((long)b * 1024 + w) * 16 + n) * 16 + m) * 3;
        ((float*)(sm + SM_PS))[tid] =
            e[0] * Wp[0] + e[1] * Wp[1] + e[2] * Wp[2] + bp[0];
    }

    ACC_DECL();
    run_gemm(sm, smb, g_PQh + abase, g_PQl + abase, 256,
             g_KVh + bbase, g_KVl + bbase, 256, 8, acc);
    stage_C(sm, acc);
    const float* Cs = (const float*)sm;

#pragma unroll
    for (int it = 0; it < 16; it++) {
        int task = it * 256 + tid;                // 4096 = 128 r x 32 f4-chunks
        int r = task >> 5, ch = task & 31;
        float4 v = *(const float4*)&Cs[r * 132 + ch * 4];
        float p = ((const float*)(sm + SM_PS))[r];
        v.x += p; v.y += p; v.z += p; v.w += p;
        int rg = r0 + r, w = rg >> 4, n = rg & 15;
        long t = (long)w * 256 + n * 16 + m;
        *(float4*)(out + ((long)b * 16384 + t) * 256 + d0 + ch * 4) = v;
    }
}

// ---------------------------------------------------------------------------
// Fused prep kernel (1D grid, 8320 blocks, 256 threads):
//   id < 8192 : VT transpose block (32w x 32d tile) that ALSO emits the
//               split Xh/Xl for the loaded elements (prep_split eliminated).
//   id >= 8192: W transpose block (32x32 tile of Wk or Wq).
// ---------------------------------------------------------------------------
__global__ __launch_bounds__(256) void prep_fused(
    const float* __restrict__ X,
    const float* __restrict__ Wk, const float* __restrict__ Wq)
{
    __shared__ float tile[32][33];
    const int id = blockIdx.x;
    const int dx = threadIdx.x & 31, dy = threadIdx.x >> 5;

    if (id < 8192) {
        // decode: (wtile 0..31, dtile 0..7, bm 0..31)
        const int wt = id & 31, dt = (id >> 5) & 7, bm = id >> 8;
        const int b = bm >> 4, m = bm & 15;
        const int w0 = wt * 32, d0 = dt * 32;
#pragma unroll
        for (int p = 0; p < 4; p++) {
            int w = w0 + dy + p * 8;
            long idx = ((long)b * 16384 + (long)w * 16 + m) * 256 + d0 + dx;
            float v = X[idx];
            tile[dy + p * 8][dx] = v;
            __nv_bfloat16 h, l; split1(v, h, l);
            g_Xh[idx] = h; g_Xl[idx] = l;        // X split emitted here
        }
        __syncthreads();
#pragma unroll
        for (int p = 0; p < 4; p++) {
            int d = d0 + dy + p * 8;
            float v = tile[dx][dy + p * 8];
            __nv_bfloat16 h, l; split1(v, h, l);
            long off = ((long)b * 256 + d) * 16384 + m * 1024 + w0 + dx;
            g_VTh[off] = h; g_VTl[off] = l;
        }
    } else {
        // W transpose: iw = 0..127 -> (isQ, ktile 0..7, ntile 0..7)
        const int iw = id - 8192;
        const int isQ = iw >> 6;
        const int k0 = ((iw >> 3) & 7) * 32, n0 = (iw & 7) * 32;
        const float* W = isQ ? Wq : Wk;
        __nv_bfloat16* TH = isQ ? g_WqTh : g_WkTh;
        __nv_bfloat16* TL = isQ ? g_WqTl : g_WkTl;
#pragma unroll
        for (int p = 0; p < 4; p++)
            tile[dy + p * 8][dx] = W[(k0 + dy + p * 8) * 256 + n0 + dx];
        __syncthreads();
#pragma unroll
        for (int p = 0; p < 4; p++) {
            float v = tile[dx][dy + p * 8];
            __nv_bfloat16 h, l; split1(v, h, l);
            int off = (n0 + dy + p * 8) * 256 + k0 + dx;
            TH[off] = h; TL[off] = l;
        }
    }
}

// ---------------------------------------------------------------------------
// Inputs (metadata order): input, embed_qk, Wq, bq, Wk, bk, Wp, bp
// ---------------------------------------------------------------------------
extern "C" void kernel_launch(void* const* d_in, const int* in_sizes, int n_in,
                              void* d_out, int out_size)
{
    const float* input = (const float*)d_in[0];
    const float* embed = (const float*)d_in[1];
    const float* Wq    = (const float*)d_in[2];
    const float* bq    = (const float*)d_in[3];
    const float* Wk    = (const float*)d_in[4];
    const float* bk    = (const float*)d_in[5];
    const float* Wp    = (const float*)d_in[6];
    const float* bp    = (const float*)d_in[7];
    float* out = (float*)d_out;

    cudaFuncSetAttribute(proj_kernel, cudaFuncAttributeMaxDynamicSharedMemorySize, SMEM_BYTES);
    cudaFuncSetAttribute(kv_kernel,   cudaFuncAttributeMaxDynamicSharedMemorySize, SMEM_BYTES);
    cudaFuncSetAttribute(att_kernel,  cudaFuncAttributeMaxDynamicSharedMemorySize, SMEM_BYTES);

    prep_fused<<<8320, 256>>>(input, Wk, Wq);

    proj_kernel<<<dim3(272, 2), 256, SMEM_BYTES>>>(bk, bq);
    kv_kernel<<<dim3(2, 2, 32), 256, SMEM_BYTES>>>();
    att_kernel<<<dim3(8, 32, 2), 256, SMEM_BYTES>>>(embed, Wp, bp, out);
}

// round 11
// speedup vs baseline: 1.2485x; 1.1729x over previous
#include <cuda_runtime.h>
#include <cuda_fp16.h>

// ---------------------------------------------------------------------------
// Round 11: fp16 precision-budgeted pipeline.
//   proj: 3-term split-fp16 (hh+hl+lh) -> phiK/phiQ essentially exact
//   kv/att: 2-term (A = exact fp16 hi+lo pair, B = single rounded fp16)
//           -> 2/3 MMA count, 3-tile stages (-25% crossbar bytes),
//              PK/KV single-buffer (halved epilogue/load traffic)
// Core geometry = R8/R10 optimum: 256 thr, 2x4 warps, 64x32 warp tiles,
// 64B-pitch XOR swizzle, 2-stage cp.async, 1 barrier/k-step, 2 CTAs/SM.
// t' = m*1024 + w token permutation. Expected rel_err ~2-5e-4 (<1e-3).
// ---------------------------------------------------------------------------

typedef unsigned int u32;

// ---------------- device buffers -------------------------------------------
__device__ __half g_Xh[2L * 16384 * 256], g_Xl[2L * 16384 * 256];
__device__ __half g_VTh[2L * 256 * 16384], g_VTl[2L * 256 * 16384];
__device__ __half g_WkTh[256 * 256], g_WkTl[256 * 256];
__device__ __half g_WqTh[256 * 256], g_WqTl[256 * 256];
__device__ __half g_PK[2L * 256 * 16384];           // phiK, single fp16
__device__ __half g_PQh[2L * 1024 * 256], g_PQl[2L * 1024 * 256];
__device__ __half g_KV[2L * 4096 * 256];            // KV, single fp16

// ---------------- smem geometry -------------------------------------------
// Tiles are 128 rows x 64B, XOR-swizzled: phys = row*64 + ((c ^ ((row>>1)&3))<<4)
#define TILE_B    8192                 // 128 * 64
#define STAGE3_B  (4 * TILE_B)         // proj: Ah, Al, Bh, Bl
#define STAGE2_B  (3 * TILE_B)         // kv/att: Ah, Al, B
#define SM_PS     67712                // scratch after Cs (128*132*4=67584)
#define SMEM_BYTES (SM_PS + 1024)      // 68736 -> 2 CTAs/SM

// ---------------- PTX helpers ---------------------------------------------
__device__ __forceinline__ u32 smem_u32(const void* p) {
    u32 a;
    asm("{ .reg .u64 t; cvta.to.shared.u64 t, %1; cvt.u32.u64 %0, t; }"
        : "=r"(a) : "l"(p));
    return a;
}
__device__ __forceinline__ void cp_async16(u32 dst, const void* src) {
    asm volatile("cp.async.cg.shared.global [%0], [%1], 16;"
                 :: "r"(dst), "l"(src));
}
#define CP_COMMIT() asm volatile("cp.async.commit_group;" ::: "memory")
#define CP_WAIT(n)  asm volatile("cp.async.wait_group %0;" :: "n"(n) : "memory")

__device__ __forceinline__ void ldmx4(u32& r0, u32& r1, u32& r2, u32& r3, u32 a) {
    asm volatile("ldmatrix.sync.aligned.m8n8.x4.shared.b16 {%0,%1,%2,%3}, [%4];"
                 : "=r"(r0), "=r"(r1), "=r"(r2), "=r"(r3) : "r"(a));
}
__device__ __forceinline__ void mma_f16(float* c, const u32* a, const u32* b) {
    asm volatile(
        "mma.sync.aligned.m16n8k16.row.col.f32.f16.f16.f32 "
        "{%0,%1,%2,%3}, {%4,%5,%6,%7}, {%8,%9}, {%0,%1,%2,%3};"
        : "+f"(c[0]), "+f"(c[1]), "+f"(c[2]), "+f"(c[3])
        : "r"(a[0]), "r"(a[1]), "r"(a[2]), "r"(a[3]), "r"(b[0]), "r"(b[1]));
}

__device__ __forceinline__ float phi_act(float z) {
    return z > 0.f ? z + 2.f : __expf(z) + 1.f;
}
__device__ __forceinline__ void split1h(float x, __half& h, __half& l) {
    h = __float2half_rn(x);
    l = __float2half_rn(x - __half2float(h));
}
__device__ __forceinline__ u32 pack_h2(__half a, __half b) {
    __half2 p; p.x = a; p.y = b;
    return *(u32*)&p;
}
// swizzled in-tile byte offset for (row, chunk16)
__device__ __forceinline__ u32 swz(u32 row, u32 c) {
    return row * 64 + ((c ^ ((row >> 1) & 3)) << 4);
}

#define ACC_DECL() float acc[4][4][4];                                   \
    _Pragma("unroll") for (int i = 0; i < 4; i++)                        \
    _Pragma("unroll") for (int j = 0; j < 4; j++)                        \
    _Pragma("unroll") for (int e = 0; e < 4; e++) acc[i][j][e] = 0.f;

// ---------------------------------------------------------------------------
// 3-term mainloop (proj): A split x B split, hh+hl+lh. 4 tiles/stage.
// ---------------------------------------------------------------------------
__device__ __forceinline__ void run_gemm3(
    char* sm, u32 smb,
    const __half* __restrict__ Ah, const __half* __restrict__ Al, long sA,
    const __half* __restrict__ Bh, const __half* __restrict__ Bl, long sB,
    int NB, float acc[4][4][4])
{
    const int tid = threadIdx.x, wid = tid >> 5, lane = tid & 31;
    const int warp_m = (wid & 1) * 64, warp_n = (wid >> 1) * 32;

    auto issue_stage = [&](int s, int kb) {
        u32 base = smb + s * STAGE3_B;
#pragma unroll
        for (int i = 0; i < 8; i++) {
            int ch = i * 256 + tid;                // 2048 chunks of 16B
            int tile = ch >> 9;
            u32 row = (ch >> 2) & 127, kc = ch & 3;
            const __half* gb =
                (tile == 0) ? Ah : (tile == 1) ? Al : (tile == 2) ? Bh : Bl;
            long st = (tile < 2) ? sA : sB;
            cp_async16(base + tile * TILE_B + swz(row, kc),
                       gb + (long)row * st + (long)kb * 32 + kc * 8);
        }
        CP_COMMIT();
    };

    const u32 arow = warp_m + (lane & 15);
    const u32 ac   = lane >> 4;
    const u32 brow = warp_n + (lane & 7) + ((lane >> 4) << 3);
    const u32 bc   = (lane >> 3) & 1;

    issue_stage(0, 0);

    for (int kb = 0; kb < NB; kb++) {
        CP_WAIT(0);
        __syncthreads();
        if (kb + 1 < NB) issue_stage((kb + 1) & 1, kb + 1);

        u32 sb = smb + (kb & 1) * STAGE3_B;

#pragma unroll
        for (int kh = 0; kh < 2; kh++) {
            u32 ah[4][4], al[4][4], bh[4][2], bl[4][2];
            const u32 aoff = swz(arow, ac + kh * 2);
            const u32 boff = swz(brow, bc + kh * 2);
#pragma unroll
            for (int i = 0; i < 4; i++) {
                ldmx4(ah[i][0], ah[i][1], ah[i][2], ah[i][3],
                      sb + aoff + i * 1024);
                ldmx4(al[i][0], al[i][1], al[i][2], al[i][3],
                      sb + TILE_B + aoff + i * 1024);
            }
#pragma unroll
            for (int j = 0; j < 2; j++) {
                ldmx4(bh[2 * j][0], bh[2 * j][1], bh[2 * j + 1][0], bh[2 * j + 1][1],
                      sb + 2 * TILE_B + boff + j * 1024);
                ldmx4(bl[2 * j][0], bl[2 * j][1], bl[2 * j + 1][0], bl[2 * j + 1][1],
                      sb + 3 * TILE_B + boff + j * 1024);
            }
#pragma unroll
            for (int i = 0; i < 4; i++)
#pragma unroll
                for (int j = 0; j < 4; j++) {
                    mma_f16(acc[i][j], ah[i], bh[j]);
                    mma_f16(acc[i][j], ah[i], bl[j]);
                    mma_f16(acc[i][j], al[i], bh[j]);
                }
        }
    }
    __syncthreads();
}

// ---------------------------------------------------------------------------
// 2-term mainloop (kv/att): A split (exact) x B single. 3 tiles/stage.
// ---------------------------------------------------------------------------
__device__ __forceinline__ void run_gemm2(
    char* sm, u32 smb,
    const __half* __restrict__ Ah, const __half* __restrict__ Al, long sA,
    const __half* __restrict__ B, long sB,
    int NB, float acc[4][4][4])
{
    const int tid = threadIdx.x, wid = tid >> 5, lane = tid & 31;
    const int warp_m = (wid & 1) * 64, warp_n = (wid >> 1) * 32;

    auto issue_stage = [&](int s, int kb) {
        u32 base = smb + s * STAGE2_B;
#pragma unroll
        for (int i = 0; i < 6; i++) {
            int ch = i * 256 + tid;                // 1536 chunks of 16B
            int tile = ch >> 9;
            u32 row = (ch >> 2) & 127, kc = ch & 3;
            const __half* gb = (tile == 0) ? Ah : (tile == 1) ? Al : B;
            long st = (tile < 2) ? sA : sB;
            cp_async16(base + tile * TILE_B + swz(row, kc),
                       gb + (long)row * st + (long)kb * 32 + kc * 8);
        }
        CP_COMMIT();
    };

    const u32 arow = warp_m + (lane & 15);
    const u32 ac   = lane >> 4;
    const u32 brow = warp_n + (lane & 7) + ((lane >> 4) << 3);
    const u32 bc   = (lane >> 3) & 1;

    issue_stage(0, 0);

    for (int kb = 0; kb < NB; kb++) {
        CP_WAIT(0);
        __syncthreads();
        if (kb + 1 < NB) issue_stage((kb + 1) & 1, kb + 1);

        u32 sb = smb + (kb & 1) * STAGE2_B;

#pragma unroll
        for (int kh = 0; kh < 2; kh++) {
            u32 ah[4][4], al[4][4], bb[4][2];
            const u32 aoff = swz(arow, ac + kh * 2);
            const u32 boff = swz(brow, bc + kh * 2);
#pragma unroll
            for (int i = 0; i < 4; i++) {
                ldmx4(ah[i][0], ah[i][1], ah[i][2], ah[i][3],
                      sb + aoff + i * 1024);
                ldmx4(al[i][0], al[i][1], al[i][2], al[i][3],
                      sb + TILE_B + aoff + i * 1024);
            }
#pragma unroll
            for (int j = 0; j < 2; j++)
                ldmx4(bb[2 * j][0], bb[2 * j][1], bb[2 * j + 1][0], bb[2 * j + 1][1],
                      sb + 2 * TILE_B + boff + j * 1024);
#pragma unroll
            for (int i = 0; i < 4; i++)
#pragma unroll
                for (int j = 0; j < 4; j++) {
                    mma_f16(acc[i][j], ah[i], bb[j]);
                    mma_f16(acc[i][j], al[i], bb[j]);
                }
        }
    }
    __syncthreads();
}

// Store per-warp accumulators into Cs[128][132] f32 (reuses stage memory).
__device__ __forceinline__ void stage_C(char* sm, float acc[4][4][4])
{
    const int tid = threadIdx.x, wid = tid >> 5, lane = tid & 31;
    const int warp_m = (wid & 1) * 64, warp_n = (wid >> 1) * 32;
    float* Cs = (float*)sm;
#pragma unroll
    for (int i = 0; i < 4; i++)
#pragma unroll
        for (int j = 0; j < 4; j++) {
            int r = warp_m + i * 16 + (lane >> 2);
            int c = warp_n + j * 8 + (lane & 3) * 2;
            *(float2*)&Cs[r * 132 + c] =
                make_float2(acc[i][j][0], acc[i][j][1]);
            *(float2*)&Cs[(r + 8) * 132 + c] =
                make_float2(acc[i][j][2], acc[i][j][3]);
        }
    __syncthreads();
}

// ---------------------------------------------------------------------------
// proj kernel: blockIdx.x<256 -> K-projection (M=c, N=tokens),
//              else            -> Q-projection (M=r, N=c).  K=256 (NB=8).
// ---------------------------------------------------------------------------
__global__ __launch_bounds__(256) void proj_kernel(
    const float* __restrict__ bk, const float* __restrict__ bq)
{
    extern __shared__ char sm[];
    u32 smb = smem_u32(sm);
    const int tid = threadIdx.x;
    const int b = blockIdx.y;
    const bool isK = blockIdx.x < 256;
    int c0, t0 = 0, r0 = 0;
    const __half *Ah, *Al, *Bh, *Bl;
    if (isK) {
        c0 = (blockIdx.x >> 7) * 128;
        t0 = (blockIdx.x & 127) * 128;
        Ah = g_WkTh + c0 * 256;  Al = g_WkTl + c0 * 256;
        Bh = g_Xh + ((long)b * 16384 + t0) * 256;
        Bl = g_Xl + ((long)b * 16384 + t0) * 256;
    } else {
        int xi = blockIdx.x - 256;
        r0 = (xi >> 1) * 128;
        c0 = (xi & 1) * 128;
        Ah = g_Xh + ((long)b * 16384 + r0) * 256;
        Al = g_Xl + ((long)b * 16384 + r0) * 256;
        Bh = g_WqTh + c0 * 256;  Bl = g_WqTl + c0 * 256;
    }

    ACC_DECL();
    run_gemm3(sm, smb, Ah, Al, 256, Bh, Bl, 256, 8, acc);
    stage_C(sm, acc);
    const float* Cs = (const float*)sm;

    if (isK) {
        const int w0 = t0 >> 4;   // 8 windows in this token tile
#pragma unroll
        for (int it = 0; it < 8; it++) {
            int task = it * 256 + tid;            // 2048 = 128 c x 16 m
            int c = task >> 4, m = task & 15;
            float bias = bk[c0 + c];
            u32 H[4];
#pragma unroll
            for (int wl = 0; wl < 4; wl++) {
                float x0 = phi_act(Cs[c * 132 + (2 * wl) * 16 + m] + bias);
                float x1 = phi_act(Cs[c * 132 + (2 * wl + 1) * 16 + m] + bias);
                H[wl] = pack_h2(__float2half_rn(x0), __float2half_rn(x1));
            }
            long off = ((long)b * 256 + c0 + c) * 16384 + m * 1024 + w0;
            *(uint4*)(g_PK + off) = make_uint4(H[0], H[1], H[2], H[3]);
        }
    } else {
#pragma unroll
        for (int it = 0; it < 8; it++) {
            int task = it * 256 + tid;            // 2048 = 128 r x 16 chunks
            int r = task >> 4, ch = task & 15;
            u32 H[4], L[4];
#pragma unroll
            for (int p = 0; p < 4; p++) {
                int col = ch * 8 + 2 * p;
                float x0 = phi_act(Cs[r * 132 + col] + bq[c0 + col]);
                float x1 = phi_act(Cs[r * 132 + col + 1] + bq[c0 + col + 1]);
                __half h0, l0, h1, l1;
                split1h(x0, h0, l0); split1h(x1, h1, l1);
                H[p] = pack_h2(h0, h1); L[p] = pack_h2(l0, l1);
            }
            long off = ((long)b * 1024 + r0 + r) * 256 + c0 + ch * 8;
            *(uint4*)(g_PQh + off) = make_uint4(H[0], H[1], H[2], H[3]);
            *(uint4*)(g_PQl + off) = make_uint4(L[0], L[1], L[2], L[3]);
        }
    }
}

// ---------------------------------------------------------------------------
// kv kernel: KVT[b][m*256+d][c] = sum_{t'} VT[d][t'] phiKT[c][t'], K=1024.
// grid (dtile=2, ctile=2, b*16+m), NB=32. 2-term: A=VT split, B=PK single.
// ---------------------------------------------------------------------------
__global__ __launch_bounds__(256) void kv_kernel()
{
    extern __shared__ char sm[];
    u32 smb = smem_u32(sm);
    const int tid = threadIdx.x;
    const int bm = blockIdx.z, b = bm >> 4, m = bm & 15;
    const int d0 = blockIdx.x * 128, c0 = blockIdx.y * 128;
    const long abase = ((long)b * 256 + d0) * 16384 + m * 1024;
    const long bbase = ((long)b * 256 + c0) * 16384 + m * 1024;

    ACC_DECL();
    run_gemm2(sm, smb, g_VTh + abase, g_VTl + abase, 16384,
              g_PK + bbase, 16384, 32, acc);
    stage_C(sm, acc);
    const float* Cs = (const float*)sm;

#pragma unroll
    for (int it = 0; it < 8; it++) {
        int task = it * 256 + tid;                // 2048 = 128 d x 16 chunks
        int d = task >> 4, ch = task & 15;
        u32 H[4];
#pragma unroll
        for (int p = 0; p < 4; p++) {
            float x0 = Cs[d * 132 + ch * 8 + 2 * p];
            float x1 = Cs[d * 132 + ch * 8 + 2 * p + 1];
            H[p] = pack_h2(__float2half_rn(x0), __float2half_rn(x1));
        }
        long off = ((long)b * 4096 + m * 256 + d0 + d) * 256 + c0 + ch * 8;
        *(uint4*)(g_KV + off) = make_uint4(H[0], H[1], H[2], H[3]);
    }
}

// ---------------------------------------------------------------------------
// att kernel: out[b][w*256+n*16+m][d] = sum_c phiQ[r][c] KVT[m*256+d][c] + p.
// grid (rtile=8, jtile=32, b). K=256 (NB=8). 2-term: A=PQ split, B=KV single.
// ---------------------------------------------------------------------------
__global__ __launch_bounds__(256) void att_kernel(
    const float* __restrict__ embed, const float* __restrict__ Wp,
    const float* __restrict__ bp, float* __restrict__ out)
{
    extern __shared__ char sm[];
    u32 smb = smem_u32(sm);
    const int tid = threadIdx.x;
    const int b = blockIdx.z;
    const int r0 = blockIdx.x * 128;
    const int j0 = blockIdx.y * 128;
    const int m = j0 >> 8, d0 = j0 & 255;
    const long abase = ((long)b * 1024 + r0) * 256;
    const long bbase = ((long)b * 4096 + j0) * 256;

    if (tid < 128) {
        int r = r0 + tid, w = r >> 4, n = r & 15;
        const float* e = embed + ((((long)b * 1024 + w) * 16 + n) * 16 + m) * 3;
        ((float*)(sm + SM_PS))[tid] =
            e[0] * Wp[0] + e[1] * Wp[1] + e[2] * Wp[2] + bp[0];
    }

    ACC_DECL();
    run_gemm2(sm, smb, g_PQh + abase, g_PQl + abase, 256,
              g_KV + bbase, 256, 8, acc);
    stage_C(sm, acc);
    const float* Cs = (const float*)sm;

#pragma unroll
    for (int it = 0; it < 16; it++) {
        int task = it * 256 + tid;                // 4096 = 128 r x 32 f4-chunks
        int r = task >> 5, ch = task & 31;
        float4 v = *(const float4*)&Cs[r * 132 + ch * 4];
        float p = ((const float*)(sm + SM_PS))[r];
        v.x += p; v.y += p; v.z += p; v.w += p;
        int rg = r0 + r, w = rg >> 4, n = rg & 15;
        long t = (long)w * 256 + n * 16 + m;
        *(float4*)(out + ((long)b * 16384 + t) * 256 + d0 + ch * 4) = v;
    }
}

// ---------------------------------------------------------------------------
// Fused prep kernel (1D grid, 8320 blocks, 256 threads):
//   id < 8192 : VT transpose block (32w x 32d) + X hi/lo split emission.
//   id >= 8192: W transpose block (32x32 tile of Wk or Wq).
// ---------------------------------------------------------------------------
__global__ __launch_bounds__(256) void prep_fused(
    const float* __restrict__ X,
    const float* __restrict__ Wk, const float* __restrict__ Wq)
{
    __shared__ float tile[32][33];
    const int id = blockIdx.x;
    const int dx = threadIdx.x & 31, dy = threadIdx.x >> 5;

    if (id < 8192) {
        const int wt = id & 31, dt = (id >> 5) & 7, bm = id >> 8;
        const int b = bm >> 4, m = bm & 15;
        const int w0 = wt * 32, d0 = dt * 32;
#pragma unroll
        for (int p = 0; p < 4; p++) {
            int w = w0 + dy + p * 8;
            long idx = ((long)b * 16384 + (long)w * 16 + m) * 256 + d0 + dx;
            float v = X[idx];
            tile[dy + p * 8][dx] = v;
            __half h, l; split1h(v, h, l);
            g_Xh[idx] = h; g_Xl[idx] = l;
        }
        __syncthreads();
#pragma unroll
        for (int p = 0; p < 4; p++) {
            int d = d0 + dy + p * 8;
            float v = tile[dx][dy + p * 8];
            __half h, l; split1h(v, h, l);
            long off = ((long)b * 256 + d) * 16384 + m * 1024 + w0 + dx;
            g_VTh[off] = h; g_VTl[off] = l;
        }
    } else {
        const int iw = id - 8192;
        const int isQ = iw >> 6;
        const int k0 = ((iw >> 3) & 7) * 32, n0 = (iw & 7) * 32;
        const float* W = isQ ? Wq : Wk;
        __half* TH = isQ ? g_WqTh : g_WkTh;
        __half* TL = isQ ? g_WqTl : g_WkTl;
#pragma unroll
        for (int p = 0; p < 4; p++)
            tile[dy + p * 8][dx] = W[(k0 + dy + p * 8) * 256 + n0 + dx];
        __syncthreads();
#pragma unroll
        for (int p = 0; p < 4; p++) {
            float v = tile[dx][dy + p * 8];
            __half h, l; split1h(v, h, l);
            int off = (n0 + dy + p * 8) * 256 + k0 + dx;
            TH[off] = h; TL[off] = l;
        }
    }
}

// ---------------------------------------------------------------------------
// Inputs (metadata order): input, embed_qk, Wq, bq, Wk, bk, Wp, bp
// ---------------------------------------------------------------------------
extern "C" void kernel_launch(void* const* d_in, const int* in_sizes, int n_in,
                              void* d_out, int out_size)
{
    const float* input = (const float*)d_in[0];
    const float* embed = (const float*)d_in[1];
    const float* Wq    = (const float*)d_in[2];
    const float* bq    = (const float*)d_in[3];
    const float* Wk    = (const float*)d_in[4];
    const float* bk    = (const float*)d_in[5];
    const float* Wp    = (const float*)d_in[6];
    const float* bp    = (const float*)d_in[7];
    float* out = (float*)d_out;

    cudaFuncSetAttribute(proj_kernel, cudaFuncAttributeMaxDynamicSharedMemorySize, SMEM_BYTES);
    cudaFuncSetAttribute(kv_kernel,   cudaFuncAttributeMaxDynamicSharedMemorySize, SMEM_BYTES);
    cudaFuncSetAttribute(att_kernel,  cudaFuncAttributeMaxDynamicSharedMemorySize, SMEM_BYTES);

    prep_fused<<<8320, 256>>>(input, Wk, Wq);

    proj_kernel<<<dim3(272, 2), 256, SMEM_BYTES>>>(bk, bq);
    kv_kernel<<<dim3(2, 2, 32), 256, SMEM_BYTES>>>();
    att_kernel<<<dim3(8, 32, 2), 256, SMEM_BYTES>>>(embed, Wp, bp, out);
}

// round 12
// speedup vs baseline: 1.9387x; 1.5528x over previous
#include <cuda_runtime.h>
#include <cuda_fp16.h>

// ---------------------------------------------------------------------------
// Round 12: full single-fp16 pipeline (1 MMA term everywhere).
// Measured norm-averaging (R11: two fp16-rounding sources -> 2.3e-5) lets all
// six operands be single fp16: expected rel_err ~5e-5, threshold 1e-3.
//   * all GEMM stages: 2 tiles (A, B) -> crossbar bytes ~halved again
//   * MMA count: proj /3, kv/att /2
//   * PK/PQ/KV single buffers; prep writes halved
// Core geometry = R8/R10 optimum: 256 thr, 2x4 warps, 64x32 warp tiles,
// 64B-pitch XOR swizzle, 2-stage cp.async, 1 barrier/k-step, 2 CTAs/SM.
// t' = m*1024 + w token permutation.
// ---------------------------------------------------------------------------

typedef unsigned int u32;

// ---------------- device buffers (single fp16) ------------------------------
__device__ __half g_X [2L * 16384 * 256];
__device__ __half g_VT[2L * 256 * 16384];
__device__ __half g_WkT[256 * 256], g_WqT[256 * 256];
__device__ __half g_PK[2L * 256 * 16384];
__device__ __half g_PQ[2L * 1024 * 256];
__device__ __half g_KV[2L * 4096 * 256];

// ---------------- smem geometry -------------------------------------------
// Tiles are 128 rows x 64B, XOR-swizzled: phys = row*64 + ((c ^ ((row>>1)&3))<<4)
#define TILE_B    8192                 // 128 * 64
#define STAGE_B   (2 * TILE_B)         // A, B
#define SM_PS     67712                // scratch after Cs (128*132*4=67584)
#define SMEM_BYTES (SM_PS + 1024)      // 68736 -> 2 CTAs/SM

// ---------------- PTX helpers ---------------------------------------------
__device__ __forceinline__ u32 smem_u32(const void* p) {
    u32 a;
    asm("{ .reg .u64 t; cvta.to.shared.u64 t, %1; cvt.u32.u64 %0, t; }"
        : "=r"(a) : "l"(p));
    return a;
}
__device__ __forceinline__ void cp_async16(u32 dst, const void* src) {
    asm volatile("cp.async.cg.shared.global [%0], [%1], 16;"
                 :: "r"(dst), "l"(src));
}
#define CP_COMMIT() asm volatile("cp.async.commit_group;" ::: "memory")
#define CP_WAIT(n)  asm volatile("cp.async.wait_group %0;" :: "n"(n) : "memory")

__device__ __forceinline__ void ldmx4(u32& r0, u32& r1, u32& r2, u32& r3, u32 a) {
    asm volatile("ldmatrix.sync.aligned.m8n8.x4.shared.b16 {%0,%1,%2,%3}, [%4];"
                 : "=r"(r0), "=r"(r1), "=r"(r2), "=r"(r3) : "r"(a));
}
__device__ __forceinline__ void mma_f16(float* c, const u32* a, const u32* b) {
    asm volatile(
        "mma.sync.aligned.m16n8k16.row.col.f32.f16.f16.f32 "
        "{%0,%1,%2,%3}, {%4,%5,%6,%7}, {%8,%9}, {%0,%1,%2,%3};"
        : "+f"(c[0]), "+f"(c[1]), "+f"(c[2]), "+f"(c[3])
        : "r"(a[0]), "r"(a[1]), "r"(a[2]), "r"(a[3]), "r"(b[0]), "r"(b[1]));
}

__device__ __forceinline__ float phi_act(float z) {
    return z > 0.f ? z + 2.f : __expf(z) + 1.f;
}
__device__ __forceinline__ u32 pack_h2(__half a, __half b) {
    __half2 p; p.x = a; p.y = b;
    return *(u32*)&p;
}
// swizzled in-tile byte offset for (row, chunk16)
__device__ __forceinline__ u32 swz(u32 row, u32 c) {
    return row * 64 + ((c ^ ((row >> 1) & 3)) << 4);
}

#define ACC_DECL() float acc[4][4][4];                                   \
    _Pragma("unroll") for (int i = 0; i < 4; i++)                        \
    _Pragma("unroll") for (int j = 0; j < 4; j++)                        \
    _Pragma("unroll") for (int e = 0; e < 4; e++) acc[i][j][e] = 0.f;

// ---------------------------------------------------------------------------
// Single-term mainloop: acc(128x128, per-warp 64x32) += A(128xK) * B(128xK)^T.
// K = NB*32. 2-stage buffer, ONE barrier per k-step, 2 tiles per stage.
// ---------------------------------------------------------------------------
__device__ __forceinline__ void run_gemm(
    char* sm, u32 smb,
    const __half* __restrict__ A, long sA,
    const __half* __restrict__ B, long sB,
    int NB, float acc[4][4][4])
{
    const int tid = threadIdx.x, wid = tid >> 5, lane = tid & 31;
    const int warp_m = (wid & 1) * 64, warp_n = (wid >> 1) * 32;

    auto issue_stage = [&](int s, int kb) {
        u32 base = smb + s * STAGE_B;
#pragma unroll
        for (int i = 0; i < 4; i++) {
            int ch = i * 256 + tid;                // 1024 chunks of 16B
            int tile = ch >> 9;
            u32 row = (ch >> 2) & 127, kc = ch & 3;
            const __half* gb = tile ? B : A;
            long st = tile ? sB : sA;
            cp_async16(base + tile * TILE_B + swz(row, kc),
                       gb + (long)row * st + (long)kb * 32 + kc * 8);
        }
        CP_COMMIT();
    };

    const u32 arow = warp_m + (lane & 15);
    const u32 ac   = lane >> 4;
    const u32 brow = warp_n + (lane & 7) + ((lane >> 4) << 3);
    const u32 bc   = (lane >> 3) & 1;

    issue_stage(0, 0);

    for (int kb = 0; kb < NB; kb++) {
        CP_WAIT(0);
        __syncthreads();
        if (kb + 1 < NB) issue_stage((kb + 1) & 1, kb + 1);

        u32 sb = smb + (kb & 1) * STAGE_B;

#pragma unroll
        for (int kh = 0; kh < 2; kh++) {
            u32 aa[4][4], bb[4][2];
            const u32 aoff = swz(arow, ac + kh * 2);
            const u32 boff = swz(brow, bc + kh * 2);
#pragma unroll
            for (int i = 0; i < 4; i++)
                ldmx4(aa[i][0], aa[i][1], aa[i][2], aa[i][3],
                      sb + aoff + i * 1024);
#pragma unroll
            for (int j = 0; j < 2; j++)
                ldmx4(bb[2 * j][0], bb[2 * j][1], bb[2 * j + 1][0], bb[2 * j + 1][1],
                      sb + TILE_B + boff + j * 1024);
#pragma unroll
            for (int i = 0; i < 4; i++)
#pragma unroll
                for (int j = 0; j < 4; j++)
                    mma_f16(acc[i][j], aa[i], bb[j]);
        }
    }
    __syncthreads();   // protect smem before epilogue staging reuses it
}

// Store per-warp accumulators into Cs[128][132] f32 (reuses stage memory).
__device__ __forceinline__ void stage_C(char* sm, float acc[4][4][4])
{
    const int tid = threadIdx.x, wid = tid >> 5, lane = tid & 31;
    const int warp_m = (wid & 1) * 64, warp_n = (wid >> 1) * 32;
    float* Cs = (float*)sm;
#pragma unroll
    for (int i = 0; i < 4; i++)
#pragma unroll
        for (int j = 0; j < 4; j++) {
            int r = warp_m + i * 16 + (lane >> 2);
            int c = warp_n + j * 8 + (lane & 3) * 2;
            *(float2*)&Cs[r * 132 + c] =
                make_float2(acc[i][j][0], acc[i][j][1]);
            *(float2*)&Cs[(r + 8) * 132 + c] =
                make_float2(acc[i][j][2], acc[i][j][3]);
        }
    __syncthreads();
}

// ---------------------------------------------------------------------------
// proj kernel: blockIdx.x<256 -> K-projection (M=c, N=tokens),
//              else            -> Q-projection (M=r, N=c).  K=256 (NB=8).
// ---------------------------------------------------------------------------
__global__ __launch_bounds__(256) void proj_kernel(
    const float* __restrict__ bk, const float* __restrict__ bq)
{
    extern __shared__ char sm[];
    u32 smb = smem_u32(sm);
    const int tid = threadIdx.x;
    const int b = blockIdx.y;
    const bool isK = blockIdx.x < 256;
    int c0, t0 = 0, r0 = 0;
    const __half *A, *B;
    if (isK) {
        c0 = (blockIdx.x >> 7) * 128;
        t0 = (blockIdx.x & 127) * 128;
        A = g_WkT + c0 * 256;
        B = g_X + ((long)b * 16384 + t0) * 256;
    } else {
        int xi = blockIdx.x - 256;
        r0 = (xi >> 1) * 128;
        c0 = (xi & 1) * 128;
        A = g_X + ((long)b * 16384 + r0) * 256;
        B = g_WqT + c0 * 256;
    }

    ACC_DECL();
    run_gemm(sm, smb, A, 256, B, 256, 8, acc);
    stage_C(sm, acc);
    const float* Cs = (const float*)sm;

    if (isK) {
        const int w0 = t0 >> 4;   // 8 windows in this token tile
#pragma unroll
        for (int it = 0; it < 8; it++) {
            int task = it * 256 + tid;            // 2048 = 128 c x 16 m
            int c = task >> 4, m = task & 15;
            float bias = bk[c0 + c];
            u32 H[4];
#pragma unroll
            for (int wl = 0; wl < 4; wl++) {
                float x0 = phi_act(Cs[c * 132 + (2 * wl) * 16 + m] + bias);
                float x1 = phi_act(Cs[c * 132 + (2 * wl + 1) * 16 + m] + bias);
                H[wl] = pack_h2(__float2half_rn(x0), __float2half_rn(x1));
            }
            long off = ((long)b * 256 + c0 + c) * 16384 + m * 1024 + w0;
            *(uint4*)(g_PK + off) = make_uint4(H[0], H[1], H[2], H[3]);
        }
    } else {
#pragma unroll
        for (int it = 0; it < 8; it++) {
            int task = it * 256 + tid;            // 2048 = 128 r x 16 chunks
            int r = task >> 4, ch = task & 15;
            u32 H[4];
#pragma unroll
            for (int p = 0; p < 4; p++) {
                int col = ch * 8 + 2 * p;
                float x0 = phi_act(Cs[r * 132 + col] + bq[c0 + col]);
                float x1 = phi_act(Cs[r * 132 + col + 1] + bq[c0 + col + 1]);
                H[p] = pack_h2(__float2half_rn(x0), __float2half_rn(x1));
            }
            long off = ((long)b * 1024 + r0 + r) * 256 + c0 + ch * 8;
            *(uint4*)(g_PQ + off) = make_uint4(H[0], H[1], H[2], H[3]);
        }
    }
}

// ---------------------------------------------------------------------------
// kv kernel: KVT[b][m*256+d][c] = sum_{t'} VT[d][t'] phiKT[c][t'], K=1024.
// grid (dtile=2, ctile=2, b*16+m), NB=32.
// ---------------------------------------------------------------------------
__global__ __launch_bounds__(256) void kv_kernel()
{
    extern __shared__ char sm[];
    u32 smb = smem_u32(sm);
    const int tid = threadIdx.x;
    const int bm = blockIdx.z, b = bm >> 4, m = bm & 15;
    const int d0 = blockIdx.x * 128, c0 = blockIdx.y * 128;
    const long abase = ((long)b * 256 + d0) * 16384 + m * 1024;
    const long bbase = ((long)b * 256 + c0) * 16384 + m * 1024;

    ACC_DECL();
    run_gemm(sm, smb, g_VT + abase, 16384, g_PK + bbase, 16384, 32, acc);
    stage_C(sm, acc);
    const float* Cs = (const float*)sm;

#pragma unroll
    for (int it = 0; it < 8; it++) {
        int task = it * 256 + tid;                // 2048 = 128 d x 16 chunks
        int d = task >> 4, ch = task & 15;
        u32 H[4];
#pragma unroll
        for (int p = 0; p < 4; p++) {
            float x0 = Cs[d * 132 + ch * 8 + 2 * p];
            float x1 = Cs[d * 132 + ch * 8 + 2 * p + 1];
            H[p] = pack_h2(__float2half_rn(x0), __float2half_rn(x1));
        }
        long off = ((long)b * 4096 + m * 256 + d0 + d) * 256 + c0 + ch * 8;
        *(uint4*)(g_KV + off) = make_uint4(H[0], H[1], H[2], H[3]);
    }
}

// ---------------------------------------------------------------------------
// att kernel: out[b][w*256+n*16+m][d] = sum_c phiQ[r][c] KVT[m*256+d][c] + p.
// grid (rtile=8, jtile=32, b). K=256 (NB=8).
// ---------------------------------------------------------------------------
__global__ __launch_bounds__(256) void att_kernel(
    const float* __restrict__ embed, const float* __restrict__ Wp,
    const float* __restrict__ bp, float* __restrict__ out)
{
    extern __shared__ char sm[];
    u32 smb = smem_u32(sm);
    const int tid = threadIdx.x;
    const int b = blockIdx.z;
    const int r0 = blockIdx.x * 128;
    const int j0 = blockIdx.y * 128;
    const int m = j0 >> 8, d0 = j0 & 255;
    const long abase = ((long)b * 1024 + r0) * 256;
    const long bbase = ((long)b * 4096 + j0) * 256;

    if (tid < 128) {
        int r = r0 + tid, w = r >> 4, n = r & 15;
        const float* e = embed + ((((long)b * 1024 + w) * 16 + n) * 16 + m) * 3;
        ((float*)(sm + SM_PS))[tid] =
            e[0] * Wp[0] + e[1] * Wp[1] + e[2] * Wp[2] + bp[0];
    }

    ACC_DECL();
    run_gemm(sm, smb, g_PQ + abase, 256, g_KV + bbase, 256, 8, acc);
    stage_C(sm, acc);
    const float* Cs = (const float*)sm;

#pragma unroll
    for (int it = 0; it < 16; it++) {
        int task = it * 256 + tid;                // 4096 = 128 r x 32 f4-chunks
        int r = task >> 5, ch = task & 31;
        float4 v = *(const float4*)&Cs[r * 132 + ch * 4];
        float p = ((const float*)(sm + SM_PS))[r];
        v.x += p; v.y += p; v.z += p; v.w += p;
        int rg = r0 + r, w = rg >> 4, n = rg & 15;
        long t = (long)w * 256 + n * 16 + m;
        *(float4*)(out + ((long)b * 16384 + t) * 256 + d0 + ch * 4) = v;
    }
}

// ---------------------------------------------------------------------------
// Fused prep kernel (1D grid, 8320 blocks, 256 threads):
//   id < 8192 : VT transpose block (32w x 32d) + X fp16 emission.
//   id >= 8192: W transpose block (32x32 tile of Wk or Wq).
// ---------------------------------------------------------------------------
__global__ __launch_bounds__(256) void prep_fused(
    const float* __restrict__ X,
    const float* __restrict__ Wk, const float* __restrict__ Wq)
{
    __shared__ float tile[32][33];
    const int id = blockIdx.x;
    const int dx = threadIdx.x & 31, dy = threadIdx.x >> 5;

    if (id < 8192) {
        const int wt = id & 31, dt = (id >> 5) & 7, bm = id >> 8;
        const int b = bm >> 4, m = bm & 15;
        const int w0 = wt * 32, d0 = dt * 32;
#pragma unroll
        for (int p = 0; p < 4; p++) {
            int w = w0 + dy + p * 8;
            long idx = ((long)b * 16384 + (long)w * 16 + m) * 256 + d0 + dx;
            float v = X[idx];
            tile[dy + p * 8][dx] = v;
            g_X[idx] = __float2half_rn(v);
        }
        __syncthreads();
#pragma unroll
        for (int p = 0; p < 4; p++) {
            int d = d0 + dy + p * 8;
            float v = tile[dx][dy + p * 8];
            long off = ((long)b * 256 + d) * 16384 + m * 1024 + w0 + dx;
            g_VT[off] = __float2half_rn(v);
        }
    } else {
        const int iw = id - 8192;
        const int isQ = iw >> 6;
        const int k0 = ((iw >> 3) & 7) * 32, n0 = (iw & 7) * 32;
        const float* W = isQ ? Wq : Wk;
        __half* T = isQ ? g_WqT : g_WkT;
#pragma unroll
        for (int p = 0; p < 4; p++)
            tile[dy + p * 8][dx] = W[(k0 + dy + p * 8) * 256 + n0 + dx];
        __syncthreads();
#pragma unroll
        for (int p = 0; p < 4; p++) {
            float v = tile[dx][dy + p * 8];
            int off = (n0 + dy + p * 8) * 256 + k0 + dx;
            T[off] = __float2half_rn(v);
        }
    }
}

// ---------------------------------------------------------------------------
// Inputs (metadata order): input, embed_qk, Wq, bq, Wk, bk, Wp, bp
// ---------------------------------------------------------------------------
extern "C" void kernel_launch(void* const* d_in, const int* in_sizes, int n_in,
                              void* d_out, int out_size)
{
    const float* input = (const float*)d_in[0];
    const float* embed = (const float*)d_in[1];
    const float* Wq    = (const float*)d_in[2];
    const float* bq    = (const float*)d_in[3];
    const float* Wk    = (const float*)d_in[4];
    const float* bk    = (const float*)d_in[5];
    const float* Wp    = (const float*)d_in[6];
    const float* bp    = (const float*)d_in[7];
    float* out = (float*)d_out;

    cudaFuncSetAttribute(proj_kernel, cudaFuncAttributeMaxDynamicSharedMemorySize, SMEM_BYTES);
    cudaFuncSetAttribute(kv_kernel,   cudaFuncAttributeMaxDynamicSharedMemorySize, SMEM_BYTES);
    cudaFuncSetAttribute(att_kernel,  cudaFuncAttributeMaxDynamicSharedMemorySize, SMEM_BYTES);

    prep_fused<<<8320, 256>>>(input, Wk, Wq);

    proj_kernel<<<dim3(272, 2), 256, SMEM_BYTES>>>(bk, bq);
    kv_kernel<<<dim3(2, 2, 32), 256, SMEM_BYTES>>>();
    att_kernel<<<dim3(8, 32, 2), 256, SMEM_BYTES>>>(embed, Wp, bp, out);
}

// round 13
// speedup vs baseline: 2.1223x; 1.0947x over previous
#include <cuda_runtime.h>
#include <cuda_fp16.h>

// ---------------------------------------------------------------------------
// Round 13: BK 32 -> 64 (half the barriers, double MMA work per sync).
// Tiles: 128 rows x 128B, swizzle phys = row*128 + ((c ^ (row&7))<<4).
// Same SMEM total (68.7KB -> 2 CTAs/SM), same regs, same fp16 numerics as
// R12 (rel_err 2.1e-4). Single-fp16 1-term GEMMs everywhere.
// Core: 256 thr, 2x4 warps, 64x32 warp tiles, 2-stage cp.async,
// 1 barrier/k-step. t' = m*1024 + w token permutation.
// ---------------------------------------------------------------------------

typedef unsigned int u32;

// ---------------- device buffers (single fp16) ------------------------------
__device__ __half g_X [2L * 16384 * 256];
__device__ __half g_VT[2L * 256 * 16384];
__device__ __half g_WkT[256 * 256], g_WqT[256 * 256];
__device__ __half g_PK[2L * 256 * 16384];
__device__ __half g_PQ[2L * 1024 * 256];
__device__ __half g_KV[2L * 4096 * 256];

// ---------------- smem geometry -------------------------------------------
#define TILE_B    16384                // 128 rows * 128B
#define STAGE_B   (2 * TILE_B)         // A, B
#define SM_PS     67712                // scratch after Cs (128*132*4=67584)
#define SMEM_BYTES (SM_PS + 1024)      // 68736 -> 2 CTAs/SM

// ---------------- PTX helpers ---------------------------------------------
__device__ __forceinline__ u32 smem_u32(const void* p) {
    u32 a;
    asm("{ .reg .u64 t; cvta.to.shared.u64 t, %1; cvt.u32.u64 %0, t; }"
        : "=r"(a) : "l"(p));
    return a;
}
__device__ __forceinline__ void cp_async16(u32 dst, const void* src) {
    asm volatile("cp.async.cg.shared.global [%0], [%1], 16;"
                 :: "r"(dst), "l"(src));
}
#define CP_COMMIT() asm volatile("cp.async.commit_group;" ::: "memory")
#define CP_WAIT(n)  asm volatile("cp.async.wait_group %0;" :: "n"(n) : "memory")

__device__ __forceinline__ void ldmx4(u32& r0, u32& r1, u32& r2, u32& r3, u32 a) {
    asm volatile("ldmatrix.sync.aligned.m8n8.x4.shared.b16 {%0,%1,%2,%3}, [%4];"
                 : "=r"(r0), "=r"(r1), "=r"(r2), "=r"(r3) : "r"(a));
}
__device__ __forceinline__ void mma_f16(float* c, const u32* a, const u32* b) {
    asm volatile(
        "mma.sync.aligned.m16n8k16.row.col.f32.f16.f16.f32 "
        "{%0,%1,%2,%3}, {%4,%5,%6,%7}, {%8,%9}, {%0,%1,%2,%3};"
        : "+f"(c[0]), "+f"(c[1]), "+f"(c[2]), "+f"(c[3])
        : "r"(a[0]), "r"(a[1]), "r"(a[2]), "r"(a[3]), "r"(b[0]), "r"(b[1]));
}

__device__ __forceinline__ float phi_act(float z) {
    return z > 0.f ? z + 2.f : __expf(z) + 1.f;
}
__device__ __forceinline__ u32 pack_h2(__half a, __half b) {
    __half2 p; p.x = a; p.y = b;
    return *(u32*)&p;
}
// swizzled in-tile byte offset for (row, chunk16 c in 0..7), 128B pitch
__device__ __forceinline__ u32 swz(u32 row, u32 c) {
    return row * 128 + ((c ^ (row & 7)) << 4);
}

#define ACC_DECL() float acc[4][4][4];                                   \
    _Pragma("unroll") for (int i = 0; i < 4; i++)                        \
    _Pragma("unroll") for (int j = 0; j < 4; j++)                        \
    _Pragma("unroll") for (int e = 0; e < 4; e++) acc[i][j][e] = 0.f;

// ---------------------------------------------------------------------------
// Single-term mainloop: acc(128x128, per-warp 64x32) += A(128xK) * B(128xK)^T.
// K = NB*64. 2-stage buffer, ONE barrier per 64-wide k-step.
// ---------------------------------------------------------------------------
__device__ __forceinline__ void run_gemm(
    char* sm, u32 smb,
    const __half* __restrict__ A, long sA,
    const __half* __restrict__ B, long sB,
    int NB, float acc[4][4][4])
{
    const int tid = threadIdx.x, wid = tid >> 5, lane = tid & 31;
    const int warp_m = (wid & 1) * 64, warp_n = (wid >> 1) * 32;

    auto issue_stage = [&](int s, int kb) {
        u32 base = smb + s * STAGE_B;
#pragma unroll
        for (int i = 0; i < 8; i++) {
            int ch = i * 256 + tid;                // 2048 chunks of 16B
            int tile = ch >> 10;
            u32 row = (ch >> 3) & 127, kc = ch & 7;
            const __half* gb = tile ? B : A;
            long st = tile ? sB : sA;
            cp_async16(base + tile * TILE_B + swz(row, kc),
                       gb + (long)row * st + (long)kb * 64 + kc * 8);
        }
        CP_COMMIT();
    };

    const u32 arow = warp_m + (lane & 15);
    const u32 ac   = lane >> 4;                    // chunk bit0
    const u32 brow = warp_n + (lane & 7) + ((lane >> 4) << 3);
    const u32 bc   = (lane >> 3) & 1;

    issue_stage(0, 0);

    for (int kb = 0; kb < NB; kb++) {
        CP_WAIT(0);
        __syncthreads();
        if (kb + 1 < NB) issue_stage((kb + 1) & 1, kb + 1);

        u32 sb = smb + (kb & 1) * STAGE_B;

#pragma unroll
        for (int kh = 0; kh < 4; kh++) {
            u32 aa[4][4], bb[4][2];
            const u32 aoff = swz(arow, ac + kh * 2);
            const u32 boff = swz(brow, bc + kh * 2);
#pragma unroll
            for (int i = 0; i < 4; i++)
                ldmx4(aa[i][0], aa[i][1], aa[i][2], aa[i][3],
                      sb + aoff + i * 2048);       // +16 rows = +2048B
#pragma unroll
            for (int j = 0; j < 2; j++)
                ldmx4(bb[2 * j][0], bb[2 * j][1], bb[2 * j + 1][0], bb[2 * j + 1][1],
                      sb + TILE_B + boff + j * 2048);
#pragma unroll
            for (int i = 0; i < 4; i++)
#pragma unroll
                for (int j = 0; j < 4; j++)
                    mma_f16(acc[i][j], aa[i], bb[j]);
        }
    }
    __syncthreads();   // protect smem before epilogue staging reuses it
}

// Store per-warp accumulators into Cs[128][132] f32 (reuses stage memory).
__device__ __forceinline__ void stage_C(char* sm, float acc[4][4][4])
{
    const int tid = threadIdx.x, wid = tid >> 5, lane = tid & 31;
    const int warp_m = (wid & 1) * 64, warp_n = (wid >> 1) * 32;
    float* Cs = (float*)sm;
#pragma unroll
    for (int i = 0; i < 4; i++)
#pragma unroll
        for (int j = 0; j < 4; j++) {
            int r = warp_m + i * 16 + (lane >> 2);
            int c = warp_n + j * 8 + (lane & 3) * 2;
            *(float2*)&Cs[r * 132 + c] =
                make_float2(acc[i][j][0], acc[i][j][1]);
            *(float2*)&Cs[(r + 8) * 132 + c] =
                make_float2(acc[i][j][2], acc[i][j][3]);
        }
    __syncthreads();
}

// ---------------------------------------------------------------------------
// proj kernel: blockIdx.x<256 -> K-projection (M=c, N=tokens),
//              else            -> Q-projection (M=r, N=c).  K=256 (NB=4).
// ---------------------------------------------------------------------------
__global__ __launch_bounds__(256) void proj_kernel(
    const float* __restrict__ bk, const float* __restrict__ bq)
{
    extern __shared__ char sm[];
    u32 smb = smem_u32(sm);
    const int tid = threadIdx.x;
    const int b = blockIdx.y;
    const bool isK = blockIdx.x < 256;
    int c0, t0 = 0, r0 = 0;
    const __half *A, *B;
    if (isK) {
        c0 = (blockIdx.x >> 7) * 128;
        t0 = (blockIdx.x & 127) * 128;
        A = g_WkT + c0 * 256;
        B = g_X + ((long)b * 16384 + t0) * 256;
    } else {
        int xi = blockIdx.x - 256;
        r0 = (xi >> 1) * 128;
        c0 = (xi & 1) * 128;
        A = g_X + ((long)b * 16384 + r0) * 256;
        B = g_WqT + c0 * 256;
    }

    ACC_DECL();
    run_gemm(sm, smb, A, 256, B, 256, 4, acc);
    stage_C(sm, acc);
    const float* Cs = (const float*)sm;

    if (isK) {
        const int w0 = t0 >> 4;   // 8 windows in this token tile
#pragma unroll
        for (int it = 0; it < 8; it++) {
            int task = it * 256 + tid;            // 2048 = 128 c x 16 m
            int c = task >> 4, m = task & 15;
            float bias = bk[c0 + c];
            u32 H[4];
#pragma unroll
            for (int wl = 0; wl < 4; wl++) {
                float x0 = phi_act(Cs[c * 132 + (2 * wl) * 16 + m] + bias);
                float x1 = phi_act(Cs[c * 132 + (2 * wl + 1) * 16 + m] + bias);
                H[wl] = pack_h2(__float2half_rn(x0), __float2half_rn(x1));
            }
            long off = ((long)b * 256 + c0 + c) * 16384 + m * 1024 + w0;
            *(uint4*)(g_PK + off) = make_uint4(H[0], H[1], H[2], H[3]);
        }
    } else {
#pragma unroll
        for (int it = 0; it < 8; it++) {
            int task = it * 256 + tid;            // 2048 = 128 r x 16 chunks
            int r = task >> 4, ch = task & 15;
            u32 H[4];
#pragma unroll
            for (int p = 0; p < 4; p++) {
                int col = ch * 8 + 2 * p;
                float x0 = phi_act(Cs[r * 132 + col] + bq[c0 + col]);
                float x1 = phi_act(Cs[r * 132 + col + 1] + bq[c0 + col + 1]);
                H[p] = pack_h2(__float2half_rn(x0), __float2half_rn(x1));
            }
            long off = ((long)b * 1024 + r0 + r) * 256 + c0 + ch * 8;
            *(uint4*)(g_PQ + off) = make_uint4(H[0], H[1], H[2], H[3]);
        }
    }
}

// ---------------------------------------------------------------------------
// kv kernel: KVT[b][m*256+d][c] = sum_{t'} VT[d][t'] phiKT[c][t'], K=1024.
// grid (dtile=2, ctile=2, b*16+m), NB=16.
// ---------------------------------------------------------------------------
__global__ __launch_bounds__(256) void kv_kernel()
{
    extern __shared__ char sm[];
    u32 smb = smem_u32(sm);
    const int tid = threadIdx.x;
    const int bm = blockIdx.z, b = bm >> 4, m = bm & 15;
    const int d0 = blockIdx.x * 128, c0 = blockIdx.y * 128;
    const long abase = ((long)b * 256 + d0) * 16384 + m * 1024;
    const long bbase = ((long)b * 256 + c0) * 16384 + m * 1024;

    ACC_DECL();
    run_gemm(sm, smb, g_VT + abase, 16384, g_PK + bbase, 16384, 16, acc);
    stage_C(sm, acc);
    const float* Cs = (const float*)sm;

#pragma unroll
    for (int it = 0; it < 8; it++) {
        int task = it * 256 + tid;                // 2048 = 128 d x 16 chunks
        int d = task >> 4, ch = task & 15;
        u32 H[4];
#pragma unroll
        for (int p = 0; p < 4; p++) {
            float x0 = Cs[d * 132 + ch * 8 + 2 * p];
            float x1 = Cs[d * 132 + ch * 8 + 2 * p + 1];
            H[p] = pack_h2(__float2half_rn(x0), __float2half_rn(x1));
        }
        long off = ((long)b * 4096 + m * 256 + d0 + d) * 256 + c0 + ch * 8;
        *(uint4*)(g_KV + off) = make_uint4(H[0], H[1], H[2], H[3]);
    }
}

// ---------------------------------------------------------------------------
// att kernel: out[b][w*256+n*16+m][d] = sum_c phiQ[r][c] KVT[m*256+d][c] + p.
// grid (rtile=8, jtile=32, b). K=256 (NB=4).
// ---------------------------------------------------------------------------
__global__ __launch_bounds__(256) void att_kernel(
    const float* __restrict__ embed, const float* __restrict__ Wp,
    const float* __restrict__ bp, float* __restrict__ out)
{
    extern __shared__ char sm[];
    u32 smb = smem_u32(sm);
    const int tid = threadIdx.x;
    const int b = blockIdx.z;
    const int r0 = blockIdx.x * 128;
    const int j0 = blockIdx.y * 128;
    const int m = j0 >> 8, d0 = j0 & 255;
    const long abase = ((long)b * 1024 + r0) * 256;
    const long bbase = ((long)b * 4096 + j0) * 256;

    if (tid < 128) {
        int r = r0 + tid, w = r >> 4, n = r & 15;
        const float* e = embed + ((((long)b * 1024 + w) * 16 + n) * 16 + m) * 3;
        ((float*)(sm + SM_PS))[tid] =
            e[0] * Wp[0] + e[1] * Wp[1] + e[2] * Wp[2] + bp[0];
    }

    ACC_DECL();
    run_gemm(sm, smb, g_PQ + abase, 256, g_KV + bbase, 256, 4, acc);
    stage_C(sm, acc);
    const float* Cs = (const float*)sm;

#pragma unroll
    for (int it = 0; it < 16; it++) {
        int task = it * 256 + tid;                // 4096 = 128 r x 32 f4-chunks
        int r = task >> 5, ch = task & 31;
        float4 v = *(const float4*)&Cs[r * 132 + ch * 4];
        float p = ((const float*)(sm + SM_PS))[r];
        v.x += p; v.y += p; v.z += p; v.w += p;
        int rg = r0 + r, w = rg >> 4, n = rg & 15;
        long t = (long)w * 256 + n * 16 + m;
        *(float4*)(out + ((long)b * 16384 + t) * 256 + d0 + ch * 4) = v;
    }
}

// ---------------------------------------------------------------------------
// Fused prep kernel (1D grid, 8320 blocks, 256 threads):
//   id < 8192 : VT transpose block (32w x 32d) + X fp16 emission.
//   id >= 8192: W transpose block (32x32 tile of Wk or Wq).
// ---------------------------------------------------------------------------
__global__ __launch_bounds__(256) void prep_fused(
    const float* __restrict__ X,
    const float* __restrict__ Wk, const float* __restrict__ Wq)
{
    __shared__ float tile[32][33];
    const int id = blockIdx.x;
    const int dx = threadIdx.x & 31, dy = threadIdx.x >> 5;

    if (id < 8192) {
        const int wt = id & 31, dt = (id >> 5) & 7, bm = id >> 8;
        const int b = bm >> 4, m = bm & 15;
        const int w0 = wt * 32, d0 = dt * 32;
#pragma unroll
        for (int p = 0; p < 4; p++) {
            int w = w0 + dy + p * 8;
            long idx = ((long)b * 16384 + (long)w * 16 + m) * 256 + d0 + dx;
            float v = X[idx];
            tile[dy + p * 8][dx] = v;
            g_X[idx] = __float2half_rn(v);
        }
        __syncthreads();
#pragma unroll
        for (int p = 0; p < 4; p++) {
            int d = d0 + dy + p * 8;
            float v = tile[dx][dy + p * 8];
            long off = ((long)b * 256 + d) * 16384 + m * 1024 + w0 + dx;
            g_VT[off] = __float2half_rn(v);
        }
    } else {
        const int iw = id - 8192;
        const int isQ = iw >> 6;
        const int k0 = ((iw >> 3) & 7) * 32, n0 = (iw & 7) * 32;
        const float* W = isQ ? Wq : Wk;
        __half* T = isQ ? g_WqT : g_WkT;
#pragma unroll
        for (int p = 0; p < 4; p++)
            tile[dy + p * 8][dx] = W[(k0 + dy + p * 8) * 256 + n0 + dx];
        __syncthreads();
#pragma unroll
        for (int p = 0; p < 4; p++) {
            float v = tile[dx][dy + p * 8];
            int off = (n0 + dy + p * 8) * 256 + k0 + dx;
            T[off] = __float2half_rn(v);
        }
    }
}

// ---------------------------------------------------------------------------
// Inputs (metadata order): input, embed_qk, Wq, bq, Wk, bk, Wp, bp
// ---------------------------------------------------------------------------
extern "C" void kernel_launch(void* const* d_in, const int* in_sizes, int n_in,
                              void* d_out, int out_size)
{
    const float* input = (const float*)d_in[0];
    const float* embed = (const float*)d_in[1];
    const float* Wq    = (const float*)d_in[2];
    const float* bq    = (const float*)d_in[3];
    const float* Wk    = (const float*)d_in[4];
    const float* bk    = (const float*)d_in[5];
    const float* Wp    = (const float*)d_in[6];
    const float* bp    = (const float*)d_in[7];
    float* out = (float*)d_out;

    cudaFuncSetAttribute(proj_kernel, cudaFuncAttributeMaxDynamicSharedMemorySize, SMEM_BYTES);
    cudaFuncSetAttribute(kv_kernel,   cudaFuncAttributeMaxDynamicSharedMemorySize, SMEM_BYTES);
    cudaFuncSetAttribute(att_kernel,  cudaFuncAttributeMaxDynamicSharedMemorySize, SMEM_BYTES);

    prep_fused<<<8320, 256>>>(input, Wk, Wq);

    proj_kernel<<<dim3(272, 2), 256, SMEM_BYTES>>>(bk, bq);
    kv_kernel<<<dim3(2, 2, 32), 256, SMEM_BYTES>>>();
    att_kernel<<<dim3(8, 32, 2), 256, SMEM_BYTES>>>(embed, Wp, bp, out);
}